// round 1
// baseline (speedup 1.0000x reference)
#include <cuda_runtime.h>
#include <cstdint>

// Problem constants
#define BATCH 256
#define CCH   64          // channels (C == H == O)
#define TLEN  4096
#define NBLK  4
#define TOUT  2048        // dilated output length
#define JC    60          // dilated outputs per CTA
#define NCHUNK 35         // ceil(2048/60)

// SMEM layout (floats)
#define WSG_STRIDE 132    // 128 cols padded; 528B rows (16B aligned, reduced STS conflicts)
#define WSG_OFF    0
#define WSG_SIZE   (128 * WSG_STRIDE)            // 16896
#define WOUT_STRIDE 68
#define WOUT_OFF   (WSG_OFF + WSG_SIZE)          // 16896
#define WOUT_SIZE  (64 * WOUT_STRIDE)            // 4352
#define G_STRIDE   65                            // odd pad -> conflict-free strided-row loads
#define G_OFF      (WOUT_OFF + WOUT_SIZE)        // 21248
#define G_SIZE     (129 * G_STRIDE)              // 8385
#define S_OFF      (G_OFF + G_SIZE)              // 29633
#define S_SIZE     (128 * G_STRIDE)              // 8320
#define GT_OFF     (S_OFF + S_SIZE)              // 37953
#define GT_SIZE    (128 * G_STRIDE)              // 8320
#define SMEM_FLOATS (GT_OFF + GT_SIZE)           // 46273
#define SMEM_BYTES  (SMEM_FLOATS * 4)            // 185092 B

__device__ __forceinline__ unsigned long long dup2(float x) {
    unsigned long long r;
    asm("mov.b64 %0, {%1, %1};" : "=l"(r) : "f"(x));
    return r;
}
__device__ __forceinline__ void fma2(unsigned long long& d, unsigned long long a, unsigned long long b) {
    asm("fma.rn.f32x2 %0, %1, %2, %0;" : "+l"(d) : "l"(a), "l"(b));
}
__device__ __forceinline__ void unpack2(unsigned long long v, float& lo, float& hi) {
    asm("mov.b64 {%0, %1}, %2;" : "=f"(lo), "=f"(hi) : "l"(v));
}

__global__ void __launch_bounds__(256, 1)
wavenet_fused_kernel(const float* __restrict__ x,
                     const float* __restrict__ sig_w, const float* __restrict__ sig_b,
                     const float* __restrict__ gate_w, const float* __restrict__ gate_b,
                     const float* __restrict__ out_w, const float* __restrict__ out_b,
                     const float* __restrict__ skip_w, const float* __restrict__ skip_b,
                     const float* __restrict__ dil_w, const float* __restrict__ dil_b,
                     float* __restrict__ out)
{
    extern __shared__ float sm[];
    float* WSG  = sm + WSG_OFF;
    float* WOUT = sm + WOUT_OFF;
    float* G    = sm + G_OFF;    // G[q][c], q=0..128, G[q]=g[tbase+q-1]
    float* S    = sm + S_OFF;    // relu(sig) per row
    float* GT   = sm + GT_OFF;   // sigmoid(gate) per row

    const int tid = threadIdx.x;
    const int w   = tid >> 5;    // warp 0..7
    const int l   = tid & 31;

    const int b     = blockIdx.y;
    const int chunk = blockIdx.x;
    const int j0    = chunk * JC;
    const int tbase = 2 * j0 - 5;

    // ---- load x tile into G (coalesced along t) ----
    const float* xb = x + (size_t)b * CCH * TLEN;
    for (int c = w; c < CCH; c += 8) {
        for (int q = l; q < 129; q += 32) {
            int t = tbase + q - 1;
            G[q * G_STRIDE + c] = (t >= 0 && t < TLEN) ? xb[c * TLEN + t] : 0.f;
        }
    }
    __syncthreads();

    const int n0  = w * 16;  // GEMM1 n-range (N=128)
    const int n0b = w * 8;   // GEMM2/3 n-range (N=64)

    // ================= 4 residual blocks =================
    for (int iblk = 0; iblk < NBLK; iblk++) {
        // ---- stage weights: WSG[k=tap*64+c][n] ; n<64 sig, n>=64 gate ----
        const float* swp = sig_w  + iblk * (CCH * CCH * 2);
        const float* gwp = gate_w + iblk * (CCH * CCH * 2);
        const float* owp = out_w  + iblk * (CCH * CCH);
        for (int idx = tid; idx < 8192; idx += 256) {
            int n = idx >> 7, c = (idx >> 1) & 63, tap = idx & 1;
            int row = ((tap << 6) + c) * WSG_STRIDE;
            WSG[row + n]      = swp[idx];
            WSG[row + 64 + n] = gwp[idx];
        }
        for (int idx = tid; idx < 4096; idx += 256) {
            int c = idx >> 6, h = idx & 63;
            WOUT[h * WOUT_STRIDE + c] = owp[idx];
        }
        __syncthreads();

        // ---- GEMM1: D[128m][128n] = A x Wsg ; A[m][tap*64+c] = G[m+tap][c]
        unsigned long long acc[4][8];
        #pragma unroll
        for (int i = 0; i < 4; i++)
            #pragma unroll
            for (int j = 0; j < 8; j++) acc[i][j] = 0ULL;

        #pragma unroll 1
        for (int tap = 0; tap < 2; tap++) {
            const float* Ab = G + tap * G_STRIDE;
            #pragma unroll 4
            for (int c = 0; c < 64; c++) {
                int k = (tap << 6) + c;
                const ulonglong2* wr = reinterpret_cast<const ulonglong2*>(WSG + k * WSG_STRIDE + n0);
                ulonglong2 p0 = wr[0], p1 = wr[1], p2 = wr[2], p3 = wr[3];
                unsigned long long bb[8] = {p0.x, p0.y, p1.x, p1.y, p2.x, p2.y, p3.x, p3.y};
                #pragma unroll
                for (int i = 0; i < 4; i++) {
                    unsigned long long a2 = dup2(Ab[(l + 32 * i) * G_STRIDE + c]);
                    #pragma unroll
                    for (int j = 0; j < 8; j++) fma2(acc[i][j], a2, bb[j]);
                }
            }
        }

        // ---- epilogue 1: relu / sigmoid, stage S & GT ----
        const float* sbp = sig_b  + iblk * 64;
        const float* gbp = gate_b + iblk * 64;
        #pragma unroll
        for (int i = 0; i < 4; i++) {
            int m = l + 32 * i;
            #pragma unroll
            for (int j = 0; j < 8; j++) {
                float v0, v1; unpack2(acc[i][j], v0, v1);
                int col0 = n0 + 2 * j;
                if (w < 4) {
                    S[m * G_STRIDE + col0]     = fmaxf(v0 + sbp[col0], 0.f);
                    S[m * G_STRIDE + col0 + 1] = fmaxf(v1 + sbp[col0 + 1], 0.f);
                } else {
                    int gc = col0 - 64;
                    float t0 = v0 + gbp[gc], t1 = v1 + gbp[gc + 1];
                    GT[m * G_STRIDE + gc]     = 1.f / (1.f + __expf(-t0));
                    GT[m * G_STRIDE + gc + 1] = 1.f / (1.f + __expf(-t1));
                }
            }
        }
        __syncthreads();

        // ---- GEMM2: D2[128m][64n] = (S*GT) x Wout ; residual update of G ----
        unsigned long long acc2[4][4];
        #pragma unroll
        for (int i = 0; i < 4; i++)
            #pragma unroll
            for (int j = 0; j < 4; j++) acc2[i][j] = 0ULL;

        #pragma unroll 4
        for (int h = 0; h < 64; h++) {
            const ulonglong2* wr = reinterpret_cast<const ulonglong2*>(WOUT + h * WOUT_STRIDE + n0b);
            ulonglong2 p0 = wr[0], p1 = wr[1];
            unsigned long long bb[4] = {p0.x, p0.y, p1.x, p1.y};
            #pragma unroll
            for (int i = 0; i < 4; i++) {
                int m = l + 32 * i;
                float a = S[m * G_STRIDE + h] * GT[m * G_STRIDE + h];
                unsigned long long a2 = dup2(a);
                #pragma unroll
                for (int j = 0; j < 4; j++) fma2(acc2[i][j], a2, bb[j]);
            }
        }

        const float* obp = out_b + iblk * 64;
        #pragma unroll
        for (int i = 0; i < 4; i++) {
            int m = l + 32 * i;
            int t = tbase + m;
            #pragma unroll
            for (int j = 0; j < 4; j++) {
                float v0, v1; unpack2(acc2[i][j], v0, v1);
                int c0 = n0b + 2 * j;
                float r0 = v0 + obp[c0]     + G[(m + 1) * G_STRIDE + c0];
                float r1 = v1 + obp[c0 + 1] + G[(m + 1) * G_STRIDE + c0 + 1];
                if (t < 0) { r0 = 0.f; r1 = 0.f; }   // causal zero-pad semantics
                G[(m + 1) * G_STRIDE + c0]     = r0;
                G[(m + 1) * G_STRIDE + c0 + 1] = r1;
            }
        }
        __syncthreads();
    }

    // ================= skip (last timestep, last chunk only) =================
    if (chunk == NCHUNK - 1 && tid < 64) {
        int q = (TLEN - 1) - tbase + 1;   // = 21
        float acc = skip_b[tid];
        #pragma unroll 8
        for (int c = 0; c < 64; c++) acc += skip_w[tid * 64 + c] * G[q * G_STRIDE + c];
        out[(size_t)BATCH * CCH * TOUT + b * 64 + tid] = acc;
    }

    // ================= dilated stride-2 conv =================
    for (int idx = tid; idx < 8192; idx += 256) {
        int cc = idx >> 7, c2 = (idx >> 1) & 63, tap = idx & 1;
        WSG[((tap << 6) + c2) * WSG_STRIDE + cc] = dil_w[idx];
    }
    __syncthreads();

    unsigned long long acc3[2][4];
    #pragma unroll
    for (int i = 0; i < 2; i++)
        #pragma unroll
        for (int j = 0; j < 4; j++) acc3[i][j] = 0ULL;

    #pragma unroll 2
    for (int k = 0; k < 128; k++) {
        int tap = k >> 6, c2 = k & 63;
        const ulonglong2* wr = reinterpret_cast<const ulonglong2*>(WSG + k * WSG_STRIDE + n0b);
        ulonglong2 p0 = wr[0], p1 = wr[1];
        unsigned long long bb[4] = {p0.x, p0.y, p1.x, p1.y};
        #pragma unroll
        for (int i = 0; i < 2; i++) {
            int jl = l + 32 * i;
            float a = (jl < JC) ? G[(2 * jl + 5 + tap) * G_STRIDE + c2] : 0.f;
            unsigned long long a2 = dup2(a);
            #pragma unroll
            for (int j = 0; j < 4; j++) fma2(acc3[i][j], a2, bb[j]);
        }
    }

    float* outb = out + (size_t)b * CCH * TOUT;
    #pragma unroll
    for (int i = 0; i < 2; i++) {
        int jl = l + 32 * i;
        int j  = j0 + jl;
        if (jl < JC && j < TOUT) {
            #pragma unroll
            for (int jj = 0; jj < 4; jj++) {
                float v0, v1; unpack2(acc3[i][jj], v0, v1);
                int c0 = n0b + 2 * jj;
                outb[c0 * TOUT + j]       = v0 + dil_b[c0];
                outb[(c0 + 1) * TOUT + j] = v1 + dil_b[c0 + 1];
            }
        }
    }
}

extern "C" void kernel_launch(void* const* d_in, const int* in_sizes, int n_in,
                              void* d_out, int out_size)
{
    (void)in_sizes; (void)n_in; (void)out_size;
    const float* x      = (const float*)d_in[0];
    const float* sig_w  = (const float*)d_in[1];
    const float* sig_b  = (const float*)d_in[2];
    const float* gate_w = (const float*)d_in[3];
    const float* gate_b = (const float*)d_in[4];
    const float* out_w  = (const float*)d_in[5];
    const float* out_b  = (const float*)d_in[6];
    const float* skip_w = (const float*)d_in[7];
    const float* skip_b = (const float*)d_in[8];
    const float* dil_w  = (const float*)d_in[9];
    const float* dil_b  = (const float*)d_in[10];
    float* out = (float*)d_out;

    cudaFuncSetAttribute(wavenet_fused_kernel,
                         cudaFuncAttributeMaxDynamicSharedMemorySize, SMEM_BYTES);

    dim3 grid(NCHUNK, BATCH, 1);
    wavenet_fused_kernel<<<grid, 256, SMEM_BYTES>>>(
        x, sig_w, sig_b, gate_w, gate_b, out_w, out_b,
        skip_w, skip_b, dil_w, dil_b, out);
}

// round 2
// speedup vs baseline: 1.1169x; 1.1169x over previous
#include <cuda_runtime.h>
#include <cstdint>

// Problem constants
#define BATCH 256
#define CCH   64
#define TLEN  4096
#define NBLK  4
#define TOUT  2048
#define JC    60
#define NCHUNK 35        // ceil(2048/60)
#define NTH   512

// SMEM layout (floats). All activation arrays store values DUPLICATED in
// pairs: arr[row][2c] == arr[row][2c+1] == value[c], so an LDS.64 yields a
// ready (v,v) operand for fma.rn.f32x2 with zero MOVs.
#define WSTR   132
#define WSG_OFF 0                         // 128 x 132  (sig||gate, col-interleaved)
#define WO2_OFF (WSG_OFF + 128*WSTR)      // 32 x 132   (out_w, k-pair packed)
#define G2_OFF  (WO2_OFF + 32*WSTR)       // 129 x 132  (duplicated activations)
#define P2_OFF  (G2_OFF + 129*WSTR)       // 128 x 132  (duplicated gated product)
#define SMEM_FLOATS (P2_OFF + 128*WSTR)   // 55044
#define SMEM_BYTES  (SMEM_FLOATS * 4)     // 220176 B
#define SD_OFF  WO2_OFF                   // dilated-output transpose buffer (64 x 61)
#define SD_STR  61

__device__ __forceinline__ void fma2(unsigned long long& d, unsigned long long a, unsigned long long b) {
    asm("fma.rn.f32x2 %0, %1, %2, %0;" : "+l"(d) : "l"(a), "l"(b));
}
__device__ __forceinline__ void unpack2(unsigned long long v, float& lo, float& hi) {
    asm("mov.b64 {%0, %1}, %2;" : "=f"(lo), "=f"(hi) : "l"(v));
}

__global__ void __launch_bounds__(NTH, 1)
wavenet_fused_kernel(const float* __restrict__ x,
                     const float* __restrict__ sig_w, const float* __restrict__ sig_b,
                     const float* __restrict__ gate_w, const float* __restrict__ gate_b,
                     const float* __restrict__ out_w, const float* __restrict__ out_b,
                     const float* __restrict__ skip_w, const float* __restrict__ skip_b,
                     const float* __restrict__ dil_w, const float* __restrict__ dil_b,
                     float* __restrict__ out)
{
    extern __shared__ float sm[];
    float* WSG = sm + WSG_OFF;
    float* WO2 = sm + WO2_OFF;
    float* G2  = sm + G2_OFF;    // G2[q][2c(+1)] = g[tbase+q-1][c]
    float* P2  = sm + P2_OFF;

    const int tid = threadIdx.x;
    const int w   = tid >> 5;    // warp 0..15
    const int l   = tid & 31;

    const int b     = blockIdx.y;
    const int chunk = blockIdx.x;
    const int j0    = chunk * JC;
    const int tbase = 2 * j0 - 5;

    // ---- load x tile into G2 (duplicated pairs) ----
    const float* xb = x + (size_t)b * CCH * TLEN;
    #pragma unroll
    for (int cc = 0; cc < 4; cc++) {
        int c = 4 * w + cc;
        const float* xc = xb + c * TLEN;
        for (int q = l; q < 129; q += 32) {
            int t = tbase + q - 1;
            float v = (t >= 0 && t < TLEN) ? xc[t] : 0.f;
            float2 d2 = make_float2(v, v);
            *reinterpret_cast<float2*>(G2 + q * WSTR + 2 * c) = d2;
        }
    }
    __syncthreads();

    // Per-lane output columns: sig/gate channels 2l, 2l+1 (GEMM1);
    // channels 2l, 2l+1 (GEMM2/dilated).
    const int m0 = 8 * w;   // 8 m-rows per warp

    // ================= 4 residual blocks =================
    for (int iblk = 0; iblk < NBLK; iblk++) {
        // ---- stage weights ----
        // WSG row k = tap*64 + c ; columns interleaved: [4h'+0,1]=sig ch 2h',2h'+1
        //                                               [4h'+2,3]=gate ch 2h',2h'+1
        const float* swp = sig_w  + iblk * 8192;
        const float* gwp = gate_w + iblk * 8192;
        const float* owp = out_w  + iblk * 4096;
        for (int idx = tid; idx < 8192; idx += NTH) {
            int h = idx >> 7, c = (idx >> 1) & 63, tap = idx & 1;
            int base = ((tap << 6) + c) * WSTR + 4 * (h >> 1) + (h & 1);
            WSG[base]     = swp[idx];
            WSG[base + 2] = gwp[idx];
        }
        // WO2 row kp packs k=2kp,2kp+1: [4l+0,1]=W[2kp][2l,2l+1], [4l+2,3]=W[2kp+1][...]
        for (int idx = tid; idx < 4096; idx += NTH) {
            int cc = idx >> 6, h = idx & 63;
            WO2[(h >> 1) * WSTR + 4 * (cc >> 1) + 2 * (h & 1) + (cc & 1)] = owp[idx];
        }
        __syncthreads();

        // ---- GEMM1: D[128m][128n'] ; A broadcast-dup from G2, B lane-consecutive ----
        unsigned long long acc[8][2];
        #pragma unroll
        for (int mm = 0; mm < 8; mm++) { acc[mm][0] = 0ULL; acc[mm][1] = 0ULL; }

        const float* Ga = G2 + m0 * WSTR;
        #pragma unroll 2
        for (int c = 0; c < 64; c++) {
            unsigned long long a2[9];
            #pragma unroll
            for (int j = 0; j < 9; j++)
                a2[j] = *reinterpret_cast<const unsigned long long*>(Ga + j * WSTR + 2 * c);
            ulonglong2 b0 = *reinterpret_cast<const ulonglong2*>(WSG + c * WSTR + 4 * l);
            ulonglong2 b1 = *reinterpret_cast<const ulonglong2*>(WSG + (64 + c) * WSTR + 4 * l);
            #pragma unroll
            for (int mm = 0; mm < 8; mm++) {
                fma2(acc[mm][0], a2[mm],     b0.x);   // sig pair, tap0
                fma2(acc[mm][1], a2[mm],     b0.y);   // gate pair, tap0
                fma2(acc[mm][0], a2[mm + 1], b1.x);   // sig pair, tap1
                fma2(acc[mm][1], a2[mm + 1], b1.y);   // gate pair, tap1
            }
        }

        // ---- epilogue 1: p = relu(s+b) * sigmoid(g+b); write duplicated P2 ----
        const float sb0 = __ldg(sig_b  + iblk * 64 + 2 * l);
        const float sb1 = __ldg(sig_b  + iblk * 64 + 2 * l + 1);
        const float gb0 = __ldg(gate_b + iblk * 64 + 2 * l);
        const float gb1 = __ldg(gate_b + iblk * 64 + 2 * l + 1);
        #pragma unroll
        for (int mm = 0; mm < 8; mm++) {
            float s0, s1, g0, g1;
            unpack2(acc[mm][0], s0, s1);
            unpack2(acc[mm][1], g0, g1);
            float p0 = fmaxf(s0 + sb0, 0.f) * (1.f / (1.f + __expf(-(g0 + gb0))));
            float p1 = fmaxf(s1 + sb1, 0.f) * (1.f / (1.f + __expf(-(g1 + gb1))));
            float4 pv = make_float4(p0, p0, p1, p1);
            *reinterpret_cast<float4*>(P2 + (m0 + mm) * WSTR + 4 * l) = pv;
        }
        __syncthreads();

        // ---- GEMM2: D2[128m][64n] = P x Wout ; residual update of G2 ----
        unsigned long long acc2[8];
        #pragma unroll
        for (int mm = 0; mm < 8; mm++) acc2[mm] = 0ULL;

        const float* Pa = P2 + m0 * WSTR;
        #pragma unroll 2
        for (int kp = 0; kp < 32; kp++) {
            ulonglong2 bv = *reinterpret_cast<const ulonglong2*>(WO2 + kp * WSTR + 4 * l);
            #pragma unroll
            for (int mm = 0; mm < 8; mm++) {
                ulonglong2 av = *reinterpret_cast<const ulonglong2*>(Pa + mm * WSTR + 4 * kp);
                fma2(acc2[mm], av.x, bv.x);
                fma2(acc2[mm], av.y, bv.y);
            }
        }

        const float ob0 = __ldg(out_b + iblk * 64 + 2 * l);
        const float ob1 = __ldg(out_b + iblk * 64 + 2 * l + 1);
        #pragma unroll
        for (int mm = 0; mm < 8; mm++) {
            int m = m0 + mm;
            float v0, v1; unpack2(acc2[mm], v0, v1);
            float4 go = *reinterpret_cast<float4*>(G2 + (m + 1) * WSTR + 4 * l);
            float r0 = v0 + ob0 + go.x;
            float r1 = v1 + ob1 + go.z;
            if (tbase + m < 0) { r0 = 0.f; r1 = 0.f; }   // causal zero-pad semantics
            float4 rv = make_float4(r0, r0, r1, r1);
            *reinterpret_cast<float4*>(G2 + (m + 1) * WSTR + 4 * l) = rv;
        }
        __syncthreads();
    }

    // ================= skip (last timestep, last chunk only) =================
    if (chunk == NCHUNK - 1 && tid < 64) {
        // t=4095 -> q = 4095 - tbase + 1 = 21
        float acc = __ldg(skip_b + tid);
        #pragma unroll 8
        for (int c = 0; c < 64; c++)
            acc += __ldg(skip_w + tid * 64 + c) * G2[21 * WSTR + 2 * c];
        out[(size_t)BATCH * CCH * TOUT + b * 64 + tid] = acc;
    }

    // ================= dilated stride-2 conv =================
    // WD2 overlays WSG. kp = tap*32 + c2/2 ; [4l+0,1]=Wd[tap,c2even][2l,2l+1], [4l+2,3]=c2odd
    for (int idx = tid; idx < 8192; idx += NTH) {
        int cc = idx >> 7, c2 = (idx >> 1) & 63, tap = idx & 1;
        int kp = tap * 32 + (c2 >> 1);
        WSG[kp * WSTR + 4 * (cc >> 1) + 2 * (c2 & 1) + (cc & 1)] = dil_w[idx];
    }
    __syncthreads();

    unsigned long long acc3[4];
    #pragma unroll
    for (int jj = 0; jj < 4; jj++) acc3[jj] = 0ULL;

    #pragma unroll 2
    for (int kp = 0; kp < 64; kp++) {
        int tap = kp >> 5, cp = kp & 31;
        ulonglong2 bv = *reinterpret_cast<const ulonglong2*>(WSG + kp * WSTR + 4 * l);
        #pragma unroll
        for (int jj = 0; jj < 4; jj++) {
            int jl = 4 * w + jj;
            int q  = 2 * jl + 5 + tap;
            if (q > 128) q = 5;  // lanes past JC compute garbage, discarded below
            ulonglong2 av = *reinterpret_cast<const ulonglong2*>(G2 + q * WSTR + 4 * cp);
            fma2(acc3[jj], av.x, bv.x);
            fma2(acc3[jj], av.y, bv.y);
        }
    }

    // transpose through SMEM (SD overlays WO2) for coalesced global stores
    float* SD = sm + SD_OFF;
    #pragma unroll
    for (int jj = 0; jj < 4; jj++) {
        int jl = 4 * w + jj;
        if (jl < JC) {
            float v0, v1; unpack2(acc3[jj], v0, v1);
            SD[(2 * l)     * SD_STR + jl] = v0;
            SD[(2 * l + 1) * SD_STR + jl] = v1;
        }
    }
    __syncthreads();

    float* outb = out + (size_t)b * CCH * TOUT;
    #pragma unroll
    for (int cc = 0; cc < 4; cc++) {
        int c = 4 * w + cc;
        float bias = __ldg(dil_b + c);
        for (int jl = l; jl < JC; jl += 32) {
            int j = j0 + jl;
            if (j < TOUT) outb[c * TOUT + j] = SD[c * SD_STR + jl] + bias;
        }
    }
}

extern "C" void kernel_launch(void* const* d_in, const int* in_sizes, int n_in,
                              void* d_out, int out_size)
{
    (void)in_sizes; (void)n_in; (void)out_size;
    const float* x      = (const float*)d_in[0];
    const float* sig_w  = (const float*)d_in[1];
    const float* sig_b  = (const float*)d_in[2];
    const float* gate_w = (const float*)d_in[3];
    const float* gate_b = (const float*)d_in[4];
    const float* out_w  = (const float*)d_in[5];
    const float* out_b  = (const float*)d_in[6];
    const float* skip_w = (const float*)d_in[7];
    const float* skip_b = (const float*)d_in[8];
    const float* dil_w  = (const float*)d_in[9];
    const float* dil_b  = (const float*)d_in[10];
    float* out = (float*)d_out;

    cudaFuncSetAttribute(wavenet_fused_kernel,
                         cudaFuncAttributeMaxDynamicSharedMemorySize, SMEM_BYTES);

    dim3 grid(NCHUNK, BATCH, 1);
    wavenet_fused_kernel<<<grid, NTH, SMEM_BYTES>>>(
        x, sig_w, sig_b, gate_w, gate_b, out_w, out_b,
        skip_w, skip_b, dil_w, dil_b, out);
}

// round 4
// speedup vs baseline: 2.2289x; 1.9956x over previous
#include <cuda_runtime.h>
#include <cstdint>

// Problem constants
#define BATCH 256
#define CCH   64
#define TLEN  4096
#define NBLK  4
#define TOUT  2048
#define JC    60
#define NCHUNK 35
#define NTH   512

// SMEM layout (floats). Strides chosen so (stride mod 32) == 4 -> fragment
// loads (8 groups x 4 lanes) hit 32 distinct banks.
#define W1_STR 132
#define W1_OFF 0
#define W1_SZ  (128 * W1_STR)            // 16896
#define W2_STR 68
#define W2_OFF (W1_OFF + W1_SZ)          // 16896
#define W2_SZ  (64 * W2_STR)             // 4352
#define G_STR  68
#define G_OFF  (W2_OFF + W2_SZ)          // 21248
#define G_SZ   (129 * G_STR)             // 8772
#define P_STR  68
#define P_OFF  (G_OFF + G_SZ)            // 30020
#define P_SZ   (128 * P_STR)             // 8704
#define SMEM_FLOATS (P_OFF + P_SZ)       // 38724
#define SMEM_BYTES  (SMEM_FLOATS * 4)    // 154896

__device__ __forceinline__ uint32_t f2tf(float x) {
    uint32_t r;
    asm("cvt.rna.tf32.f32 %0, %1;" : "=r"(r) : "f"(x));
    return r;
}
__device__ __forceinline__ void mma8(float d[4], const uint32_t a[4],
                                     uint32_t b0, uint32_t b1) {
    asm volatile(
        "mma.sync.aligned.m16n8k8.row.col.f32.tf32.tf32.f32 "
        "{%0,%1,%2,%3}, {%4,%5,%6,%7}, {%8,%9}, {%0,%1,%2,%3};"
        : "+f"(d[0]), "+f"(d[1]), "+f"(d[2]), "+f"(d[3])
        : "r"(a[0]), "r"(a[1]), "r"(a[2]), "r"(a[3]), "r"(b0), "r"(b1));
}

__global__ void __launch_bounds__(NTH, 1)
wavenet_mma_kernel(const float* __restrict__ x,
                   const float* __restrict__ sig_w, const float* __restrict__ sig_b,
                   const float* __restrict__ gate_w, const float* __restrict__ gate_b,
                   const float* __restrict__ out_w, const float* __restrict__ out_b,
                   const float* __restrict__ skip_w, const float* __restrict__ skip_b,
                   const float* __restrict__ dil_w, const float* __restrict__ dil_b,
                   float* __restrict__ out)
{
    extern __shared__ float sm[];
    uint32_t* W1u = (uint32_t*)(sm + W1_OFF);   // B1 [n=128][k=128] tf32 (also W3)
    uint32_t* W2u = (uint32_t*)(sm + W2_OFF);   // B2 [n=64][k=64] tf32
    float*    G   = sm + G_OFF;                  // G[q][c], q=0..128, stride 68
    float*    P   = sm + P_OFF;                  // gate sigmoid, then gated product
    uint32_t* Pu  = (uint32_t*)P;
    float*    SD  = P;                           // dilated-output transpose buffer

    const int tid = threadIdx.x;
    const int w   = tid >> 5;
    const int l   = tid & 31;
    const int g   = l >> 2;     // mma group id (0..7)
    const int t   = l & 3;      // thread in group
    const int wm  = w >> 2;     // m-block (rows 32*wm .. +32)
    const int wn  = w & 3;      // n-block

    const int b     = blockIdx.y;
    const int chunk = blockIdx.x;
    const int j0    = chunk * JC;
    const int tbase = 2 * j0 - 5;

    // ---- load x tile into G ----
    const float* xb = x + (size_t)b * CCH * TLEN;
    for (int c = w; c < CCH; c += 16) {
        const float* xc = xb + c * TLEN;
        for (int q = l; q < 129; q += 32) {
            int tt = tbase + q - 1;
            G[q * G_STR + c] = (tt >= 0 && tt < TLEN) ? xc[tt] : 0.f;
        }
    }
    __syncthreads();

    // ================= 4 residual blocks =================
    for (int iblk = 0; iblk < NBLK; iblk++) {
        // ---- stage weights (tf32-rounded) ----
        const float* swp = sig_w  + iblk * 8192;
        const float* gwp = gate_w + iblk * 8192;
        const float* owp = out_w  + iblk * 4096;
        for (int idx = tid; idx < 8192; idx += NTH) {
            int h = idx >> 7, c = (idx >> 1) & 63, tap = idx & 1;
            int k = (tap << 6) + c;
            W1u[h * W1_STR + k]        = f2tf(swp[idx]);
            W1u[(h + 64) * W1_STR + k] = f2tf(gwp[idx]);
        }
        for (int idx = tid; idx < 4096; idx += NTH) {
            int c = idx >> 6, h = idx & 63;
            W2u[c * W2_STR + h] = f2tf(owp[idx]);
        }
        __syncthreads();

        // ---- GEMM1: D1[128m][128n] = A x W1^T ; A[m][tap*64+c] = G[m+tap][c]
        float acc1[2][4][4];
        #pragma unroll
        for (int mi = 0; mi < 2; mi++)
            #pragma unroll
            for (int ni = 0; ni < 4; ni++)
                #pragma unroll
                for (int q = 0; q < 4; q++) acc1[mi][ni][q] = 0.f;

        #pragma unroll
        for (int kt = 0; kt < 16; kt++) {
            const int tap = kt >> 3, c0 = (kt & 7) * 8;
            uint32_t a[2][4];
            #pragma unroll
            for (int mi = 0; mi < 2; mi++) {
                const float* gp = G + (32 * wm + 16 * mi + g + tap) * G_STR + c0 + t;
                a[mi][0] = f2tf(gp[0]);
                a[mi][1] = f2tf(gp[8 * G_STR]);
                a[mi][2] = f2tf(gp[4]);
                a[mi][3] = f2tf(gp[8 * G_STR + 4]);
            }
            #pragma unroll
            for (int ni = 0; ni < 4; ni++) {
                const uint32_t* bp = W1u + (32 * wn + 8 * ni + g) * W1_STR + kt * 8 + t;
                uint32_t b0 = bp[0], b1 = bp[4];
                mma8(acc1[0][ni], a[0], b0, b1);
                mma8(acc1[1][ni], a[1], b0, b1);
            }
        }

        // ---- epilogue 1 ----
        if (wn >= 2) {  // gate half: write sigmoid to P
            #pragma unroll
            for (int mi = 0; mi < 2; mi++)
                #pragma unroll
                for (int ni = 0; ni < 4; ni++) {
                    int r  = 32 * wm + 16 * mi + g;
                    int gc = 32 * (wn - 2) + 8 * ni + 2 * t;
                    float gb0 = __ldg(gate_b + iblk * 64 + gc);
                    float gb1 = __ldg(gate_b + iblk * 64 + gc + 1);
                    P[r * P_STR + gc]           = 1.f / (1.f + __expf(-(acc1[mi][ni][0] + gb0)));
                    P[r * P_STR + gc + 1]       = 1.f / (1.f + __expf(-(acc1[mi][ni][1] + gb1)));
                    P[(r + 8) * P_STR + gc]     = 1.f / (1.f + __expf(-(acc1[mi][ni][2] + gb0)));
                    P[(r + 8) * P_STR + gc + 1] = 1.f / (1.f + __expf(-(acc1[mi][ni][3] + gb1)));
                }
        }
        __syncthreads();
        if (wn < 2) {   // sig half: p = relu(s+b)*sigmoid -> overwrite P (tf32)
            #pragma unroll
            for (int mi = 0; mi < 2; mi++)
                #pragma unroll
                for (int ni = 0; ni < 4; ni++) {
                    int r  = 32 * wm + 16 * mi + g;
                    int sc = 32 * wn + 8 * ni + 2 * t;
                    float sb0 = __ldg(sig_b + iblk * 64 + sc);
                    float sb1 = __ldg(sig_b + iblk * 64 + sc + 1);
                    float p00 = fmaxf(acc1[mi][ni][0] + sb0, 0.f) * P[r * P_STR + sc];
                    float p01 = fmaxf(acc1[mi][ni][1] + sb1, 0.f) * P[r * P_STR + sc + 1];
                    float p10 = fmaxf(acc1[mi][ni][2] + sb0, 0.f) * P[(r + 8) * P_STR + sc];
                    float p11 = fmaxf(acc1[mi][ni][3] + sb1, 0.f) * P[(r + 8) * P_STR + sc + 1];
                    Pu[r * P_STR + sc]           = f2tf(p00);
                    Pu[r * P_STR + sc + 1]       = f2tf(p01);
                    Pu[(r + 8) * P_STR + sc]     = f2tf(p10);
                    Pu[(r + 8) * P_STR + sc + 1] = f2tf(p11);
                }
        }
        __syncthreads();

        // ---- GEMM2: D2[128m][64n] = P x W2^T (K=64) ----
        float acc2[2][2][4];
        #pragma unroll
        for (int mi = 0; mi < 2; mi++)
            #pragma unroll
            for (int ni = 0; ni < 2; ni++)
                #pragma unroll
                for (int q = 0; q < 4; q++) acc2[mi][ni][q] = 0.f;

        #pragma unroll
        for (int kt = 0; kt < 8; kt++) {
            uint32_t a[2][4];
            #pragma unroll
            for (int mi = 0; mi < 2; mi++) {
                const uint32_t* pp = Pu + (32 * wm + 16 * mi + g) * P_STR + kt * 8 + t;
                a[mi][0] = pp[0];
                a[mi][1] = pp[8 * P_STR];
                a[mi][2] = pp[4];
                a[mi][3] = pp[8 * P_STR + 4];
            }
            #pragma unroll
            for (int ni = 0; ni < 2; ni++) {
                const uint32_t* bp = W2u + (16 * wn + 8 * ni + g) * W2_STR + kt * 8 + t;
                uint32_t b0 = bp[0], b1 = bp[4];
                mma8(acc2[0][ni], a[0], b0, b1);
                mma8(acc2[1][ni], a[1], b0, b1);
            }
        }

        // ---- epilogue 2: residual update of G ----
        #pragma unroll
        for (int mi = 0; mi < 2; mi++)
            #pragma unroll
            for (int ni = 0; ni < 2; ni++) {
                int r0 = 32 * wm + 16 * mi + g;
                int c0 = 16 * wn + 8 * ni + 2 * t;
                float ob0 = __ldg(out_b + iblk * 64 + c0);
                float ob1 = __ldg(out_b + iblk * 64 + c0 + 1);
                float* gp0 = G + (r0 + 1) * G_STR + c0;
                float* gp1 = G + (r0 + 9) * G_STR + c0;
                float v00 = acc2[mi][ni][0] + ob0 + gp0[0];
                float v01 = acc2[mi][ni][1] + ob1 + gp0[1];
                float v10 = acc2[mi][ni][2] + ob0 + gp1[0];
                float v11 = acc2[mi][ni][3] + ob1 + gp1[1];
                if (tbase + r0 < 0)     { v00 = 0.f; v01 = 0.f; }
                if (tbase + r0 + 8 < 0) { v10 = 0.f; v11 = 0.f; }
                gp0[0] = v00; gp0[1] = v01;
                gp1[0] = v10; gp1[1] = v11;
            }
        __syncthreads();
    }

    // ================= skip (last timestep, last chunk only) =================
    if (chunk == NCHUNK - 1 && tid < 64) {
        float acc = __ldg(skip_b + tid);   // t=4095 -> q=21
        #pragma unroll 8
        for (int c = 0; c < 64; c++)
            acc += __ldg(skip_w + tid * 64 + c) * G[21 * G_STR + c];
        out[(size_t)BATCH * CCH * TOUT + b * 64 + tid] = acc;
    }

    // ================= dilated stride-2 conv (GEMM3, M=64) =================
    for (int idx = tid; idx < 8192; idx += NTH) {
        int cc = idx >> 7, c2 = (idx >> 1) & 63, tap = idx & 1;
        W1u[cc * W1_STR + (tap << 6) + c2] = f2tf(dil_w[idx]);
    }
    __syncthreads();

    const int wm3 = w >> 3;   // 0..1 : rows 32
    const int wn3 = w & 7;    // 0..7 : cols 8
    float acc3[2][4];
    #pragma unroll
    for (int mi = 0; mi < 2; mi++)
        #pragma unroll
        for (int q = 0; q < 4; q++) acc3[mi][q] = 0.f;

    #pragma unroll
    for (int kt = 0; kt < 16; kt++) {
        const int tap = kt >> 3, c0 = (kt & 7) * 8;
        uint32_t a[2][4];
        #pragma unroll
        for (int mi = 0; mi < 2; mi++) {
            int jl = 32 * wm3 + 16 * mi + g;
            int q0 = 2 * jl + 5 + tap;       if (q0 > 128) q0 = 128;
            int q1 = 2 * (jl + 8) + 5 + tap; if (q1 > 128) q1 = 128;
            a[mi][0] = f2tf(G[q0 * G_STR + c0 + t]);
            a[mi][1] = f2tf(G[q1 * G_STR + c0 + t]);
            a[mi][2] = f2tf(G[q0 * G_STR + c0 + t + 4]);
            a[mi][3] = f2tf(G[q1 * G_STR + c0 + t + 4]);
        }
        const uint32_t* bp = W1u + (8 * wn3 + g) * W1_STR + kt * 8 + t;
        uint32_t b0 = bp[0], b1 = bp[4];
        mma8(acc3[0], a[0], b0, b1);
        mma8(acc3[1], a[1], b0, b1);
    }

    // epilogue 3: transpose through SMEM (SD overlays P)
    {
        int cc0 = 8 * wn3 + 2 * t;
        float db0 = __ldg(dil_b + cc0);
        float db1 = __ldg(dil_b + cc0 + 1);
        #pragma unroll
        for (int mi = 0; mi < 2; mi++) {
            int jl0 = 32 * wm3 + 16 * mi + g;
            if (jl0 < JC) {
                SD[cc0 * P_STR + jl0]       = acc3[mi][0] + db0;
                SD[(cc0 + 1) * P_STR + jl0] = acc3[mi][1] + db1;
            }
            int jl1 = jl0 + 8;
            if (jl1 < JC) {
                SD[cc0 * P_STR + jl1]       = acc3[mi][2] + db0;
                SD[(cc0 + 1) * P_STR + jl1] = acc3[mi][3] + db1;
            }
        }
    }
    __syncthreads();

    float* outb = out + (size_t)b * CCH * TOUT;
    #pragma unroll
    for (int cc = 0; cc < 4; cc++) {
        int c = 4 * w + cc;
        for (int jl = l; jl < JC; jl += 32) {
            int j = j0 + jl;
            if (j < TOUT) outb[c * TOUT + j] = SD[c * P_STR + jl];
        }
    }
}

extern "C" void kernel_launch(void* const* d_in, const int* in_sizes, int n_in,
                              void* d_out, int out_size)
{
    (void)in_sizes; (void)n_in; (void)out_size;
    const float* x      = (const float*)d_in[0];
    const float* sig_w  = (const float*)d_in[1];
    const float* sig_b  = (const float*)d_in[2];
    const float* gate_w = (const float*)d_in[3];
    const float* gate_b = (const float*)d_in[4];
    const float* out_w  = (const float*)d_in[5];
    const float* out_b  = (const float*)d_in[6];
    const float* skip_w = (const float*)d_in[7];
    const float* skip_b = (const float*)d_in[8];
    const float* dil_w  = (const float*)d_in[9];
    const float* dil_b  = (const float*)d_in[10];
    float* out = (float*)d_out;

    cudaFuncSetAttribute(wavenet_mma_kernel,
                         cudaFuncAttributeMaxDynamicSharedMemorySize, SMEM_BYTES);

    dim3 grid(NCHUNK, BATCH, 1);
    wavenet_mma_kernel<<<grid, NTH, SMEM_BYTES>>>(
        x, sig_w, sig_b, gate_w, gate_b, out_w, out_b,
        skip_w, skip_b, dil_w, dil_b, out);
}

// round 5
// speedup vs baseline: 3.1315x; 1.4049x over previous
#include <cuda_runtime.h>
#include <cstdint>

// Problem constants
#define BATCH 256
#define CCH   64
#define TLEN  4096
#define NBLK  4
#define TOUT  2048
#define JC    60
#define NCHUNK 35
#define NTH   512

// SMEM layout (floats). Strides mod 32 == 4 -> fragment loads conflict-free.
#define W_STR  132
#define W_OFF  0
#define W_SZ   (64 * W_STR)              // 8448 : one 64xK=128 weight panel
#define G_STR  68
#define G_OFF  (W_OFF + W_SZ)            // 8448 : G[129][64]
#define G_SZ   (129 * G_STR)             // 8772
#define P_STR  68
#define P_OFF  (G_OFF + G_SZ)            // 17220 : sigmoid, then gated product
#define P_SZ   (128 * P_STR)             // 8704
#define SMEM_FLOATS (P_OFF + P_SZ)       // 25924
#define SMEM_BYTES  (SMEM_FLOATS * 4)    // 103696 -> 2 CTAs/SM

__device__ __forceinline__ void mma8(float d[4], const uint32_t a[4],
                                     uint32_t b0, uint32_t b1) {
    asm volatile(
        "mma.sync.aligned.m16n8k8.row.col.f32.tf32.tf32.f32 "
        "{%0,%1,%2,%3}, {%4,%5,%6,%7}, {%8,%9}, {%0,%1,%2,%3};"
        : "+f"(d[0]), "+f"(d[1]), "+f"(d[2]), "+f"(d[3])
        : "r"(a[0]), "r"(a[1]), "r"(a[2]), "r"(a[3]), "r"(b0), "r"(b1));
}

__global__ void __launch_bounds__(NTH, 2)
wavenet_mma_kernel(const float* __restrict__ x,
                   const float* __restrict__ sig_w, const float* __restrict__ sig_b,
                   const float* __restrict__ gate_w, const float* __restrict__ gate_b,
                   const float* __restrict__ out_w, const float* __restrict__ out_b,
                   const float* __restrict__ skip_w, const float* __restrict__ skip_b,
                   const float* __restrict__ dil_w, const float* __restrict__ dil_b,
                   float* __restrict__ out)
{
    extern __shared__ float sm[];
    float*    W   = sm + W_OFF;          // staged weight panel [n<=64][k<=128]
    uint32_t* Wu  = (uint32_t*)W;
    float*    G   = sm + G_OFF;          // G[q][c], q=0..128
    uint32_t* Gu  = (uint32_t*)G;
    float*    P   = sm + P_OFF;
    uint32_t* Pu  = (uint32_t*)P;
    float*    SD  = P;                   // dilated transpose buffer (overlay)

    const int tid = threadIdx.x;
    const int w   = tid >> 5;
    const int l   = tid & 31;
    const int g   = l >> 2;     // mma group id (0..7)
    const int t   = l & 3;      // thread in group
    const int wm  = w >> 2;     // m-block (rows 32*wm..+32)
    const int wn  = w & 3;      // n-block (cols 16*wn..+16)

    const int b     = blockIdx.y;
    const int chunk = blockIdx.x;
    const int j0    = chunk * JC;
    const int tbase = 2 * j0 - 5;

    // ---- load x tile into G ----
    const float* xb = x + (size_t)b * CCH * TLEN;
    for (int c = w; c < CCH; c += 16) {
        const float* xc = xb + c * TLEN;
        for (int q = l; q < 129; q += 32) {
            int tt = tbase + q - 1;
            G[q * G_STR + c] = (tt >= 0 && tt < TLEN) ? xc[tt] : 0.f;
        }
    }

    // ================= 4 residual blocks =================
    for (int iblk = 0; iblk < NBLK; iblk++) {
        const float* swp = sig_w  + iblk * 8192;   // [h][c][tap]
        const float* gwp = gate_w + iblk * 8192;
        const float* owp = out_w  + iblk * 4096;   // [c][h]

        // ---------- phase A: gate half ----------
        __syncthreads();
        for (int idx = tid; idx < 8192; idx += NTH) {
            int h = idx >> 7, k = idx & 127;
            W[h * W_STR + k] = gwp[h * 128 + (k & 63) * 2 + (k >> 6)];
        }
        __syncthreads();

        {
            float acc[2][2][4];
            #pragma unroll
            for (int mi = 0; mi < 2; mi++)
                #pragma unroll
                for (int ni = 0; ni < 2; ni++)
                    #pragma unroll
                    for (int q = 0; q < 4; q++) acc[mi][ni][q] = 0.f;

            #pragma unroll
            for (int kt = 0; kt < 16; kt++) {
                const int tap = kt >> 3, c0 = (kt & 7) * 8;
                uint32_t a[2][4];
                #pragma unroll
                for (int mi = 0; mi < 2; mi++) {
                    const uint32_t* gp = Gu + (32 * wm + 16 * mi + g + tap) * G_STR + c0 + t;
                    a[mi][0] = gp[0];
                    a[mi][1] = gp[8 * G_STR];
                    a[mi][2] = gp[4];
                    a[mi][3] = gp[8 * G_STR + 4];
                }
                #pragma unroll
                for (int ni = 0; ni < 2; ni++) {
                    const uint32_t* bp = Wu + (16 * wn + 8 * ni + g) * W_STR + kt * 8 + t;
                    uint32_t b0 = bp[0], b1 = bp[4];
                    mma8(acc[0][ni], a[0], b0, b1);
                    mma8(acc[1][ni], a[1], b0, b1);
                }
            }
            // epilogue: sigmoid -> P
            #pragma unroll
            for (int mi = 0; mi < 2; mi++)
                #pragma unroll
                for (int ni = 0; ni < 2; ni++) {
                    int r  = 32 * wm + 16 * mi + g;
                    int gc = 16 * wn + 8 * ni + 2 * t;
                    float gb0 = __ldg(gate_b + iblk * 64 + gc);
                    float gb1 = __ldg(gate_b + iblk * 64 + gc + 1);
                    P[r * P_STR + gc]           = 1.f / (1.f + __expf(-(acc[mi][ni][0] + gb0)));
                    P[r * P_STR + gc + 1]       = 1.f / (1.f + __expf(-(acc[mi][ni][1] + gb1)));
                    P[(r + 8) * P_STR + gc]     = 1.f / (1.f + __expf(-(acc[mi][ni][2] + gb0)));
                    P[(r + 8) * P_STR + gc + 1] = 1.f / (1.f + __expf(-(acc[mi][ni][3] + gb1)));
                }
        }
        __syncthreads();

        // ---------- phase B: sig half ----------
        for (int idx = tid; idx < 8192; idx += NTH) {
            int h = idx >> 7, k = idx & 127;
            W[h * W_STR + k] = swp[h * 128 + (k & 63) * 2 + (k >> 6)];
        }
        __syncthreads();

        {
            float acc[2][2][4];
            #pragma unroll
            for (int mi = 0; mi < 2; mi++)
                #pragma unroll
                for (int ni = 0; ni < 2; ni++)
                    #pragma unroll
                    for (int q = 0; q < 4; q++) acc[mi][ni][q] = 0.f;

            #pragma unroll
            for (int kt = 0; kt < 16; kt++) {
                const int tap = kt >> 3, c0 = (kt & 7) * 8;
                uint32_t a[2][4];
                #pragma unroll
                for (int mi = 0; mi < 2; mi++) {
                    const uint32_t* gp = Gu + (32 * wm + 16 * mi + g + tap) * G_STR + c0 + t;
                    a[mi][0] = gp[0];
                    a[mi][1] = gp[8 * G_STR];
                    a[mi][2] = gp[4];
                    a[mi][3] = gp[8 * G_STR + 4];
                }
                #pragma unroll
                for (int ni = 0; ni < 2; ni++) {
                    const uint32_t* bp = Wu + (16 * wn + 8 * ni + g) * W_STR + kt * 8 + t;
                    uint32_t b0 = bp[0], b1 = bp[4];
                    mma8(acc[0][ni], a[0], b0, b1);
                    mma8(acc[1][ni], a[1], b0, b1);
                }
            }
            // epilogue: p = relu(s+b) * sigmoid (in-place on P)
            #pragma unroll
            for (int mi = 0; mi < 2; mi++)
                #pragma unroll
                for (int ni = 0; ni < 2; ni++) {
                    int r  = 32 * wm + 16 * mi + g;
                    int sc = 16 * wn + 8 * ni + 2 * t;
                    float sb0 = __ldg(sig_b + iblk * 64 + sc);
                    float sb1 = __ldg(sig_b + iblk * 64 + sc + 1);
                    P[r * P_STR + sc]           = fmaxf(acc[mi][ni][0] + sb0, 0.f) * P[r * P_STR + sc];
                    P[r * P_STR + sc + 1]       = fmaxf(acc[mi][ni][1] + sb1, 0.f) * P[r * P_STR + sc + 1];
                    P[(r + 8) * P_STR + sc]     = fmaxf(acc[mi][ni][2] + sb0, 0.f) * P[(r + 8) * P_STR + sc];
                    P[(r + 8) * P_STR + sc + 1] = fmaxf(acc[mi][ni][3] + sb1, 0.f) * P[(r + 8) * P_STR + sc + 1];
                }
        }
        __syncthreads();

        // ---------- phase C: 1x1 out conv + residual ----------
        for (int idx = tid; idx < 4096; idx += NTH) {
            int c = idx >> 6, h = idx & 63;
            W[c * W_STR + h] = owp[idx];
        }
        __syncthreads();

        {
            float acc[2][2][4];
            #pragma unroll
            for (int mi = 0; mi < 2; mi++)
                #pragma unroll
                for (int ni = 0; ni < 2; ni++)
                    #pragma unroll
                    for (int q = 0; q < 4; q++) acc[mi][ni][q] = 0.f;

            #pragma unroll
            for (int kt = 0; kt < 8; kt++) {
                uint32_t a[2][4];
                #pragma unroll
                for (int mi = 0; mi < 2; mi++) {
                    const uint32_t* pp = Pu + (32 * wm + 16 * mi + g) * P_STR + kt * 8 + t;
                    a[mi][0] = pp[0];
                    a[mi][1] = pp[8 * P_STR];
                    a[mi][2] = pp[4];
                    a[mi][3] = pp[8 * P_STR + 4];
                }
                #pragma unroll
                for (int ni = 0; ni < 2; ni++) {
                    const uint32_t* bp = Wu + (16 * wn + 8 * ni + g) * W_STR + kt * 8 + t;
                    uint32_t b0 = bp[0], b1 = bp[4];
                    mma8(acc[0][ni], a[0], b0, b1);
                    mma8(acc[1][ni], a[1], b0, b1);
                }
            }
            // epilogue: residual update of G
            #pragma unroll
            for (int mi = 0; mi < 2; mi++)
                #pragma unroll
                for (int ni = 0; ni < 2; ni++) {
                    int r0 = 32 * wm + 16 * mi + g;
                    int c0 = 16 * wn + 8 * ni + 2 * t;
                    float ob0 = __ldg(out_b + iblk * 64 + c0);
                    float ob1 = __ldg(out_b + iblk * 64 + c0 + 1);
                    float* gp0 = G + (r0 + 1) * G_STR + c0;
                    float* gp1 = G + (r0 + 9) * G_STR + c0;
                    float v00 = acc[mi][ni][0] + ob0 + gp0[0];
                    float v01 = acc[mi][ni][1] + ob1 + gp0[1];
                    float v10 = acc[mi][ni][2] + ob0 + gp1[0];
                    float v11 = acc[mi][ni][3] + ob1 + gp1[1];
                    if (tbase + r0 < 0)     { v00 = 0.f; v01 = 0.f; }
                    if (tbase + r0 + 8 < 0) { v10 = 0.f; v11 = 0.f; }
                    gp0[0] = v00; gp0[1] = v01;
                    gp1[0] = v10; gp1[1] = v11;
                }
        }
    }
    __syncthreads();

    // ================= skip (last timestep, last chunk only) =================
    if (chunk == NCHUNK - 1 && tid < 64) {
        float acc = __ldg(skip_b + tid);   // t=4095 -> q=21
        #pragma unroll 8
        for (int c = 0; c < 64; c++)
            acc += __ldg(skip_w + tid * 64 + c) * G[21 * G_STR + c];
        out[(size_t)BATCH * CCH * TOUT + b * 64 + tid] = acc;
    }

    // ================= dilated stride-2 conv (GEMM3, M=64) =================
    for (int idx = tid; idx < 8192; idx += NTH) {
        int cc = idx >> 7, k = idx & 127;
        W[cc * W_STR + k] = dil_w[cc * 128 + (k & 63) * 2 + (k >> 6)];
    }
    __syncthreads();

    const int wm3 = w >> 3;   // 0..1 : 32 rows each
    const int wn3 = w & 7;    // 0..7 : 8 cols each
    float acc3[2][4];
    #pragma unroll
    for (int mi = 0; mi < 2; mi++)
        #pragma unroll
        for (int q = 0; q < 4; q++) acc3[mi][q] = 0.f;

    #pragma unroll
    for (int kt = 0; kt < 16; kt++) {
        const int tap = kt >> 3, c0 = (kt & 7) * 8;
        uint32_t a[2][4];
        #pragma unroll
        for (int mi = 0; mi < 2; mi++) {
            int jl = 32 * wm3 + 16 * mi + g;
            int q0 = 2 * jl + 5 + tap;       if (q0 > 128) q0 = 128;
            int q1 = 2 * (jl + 8) + 5 + tap; if (q1 > 128) q1 = 128;
            a[mi][0] = Gu[q0 * G_STR + c0 + t];
            a[mi][1] = Gu[q1 * G_STR + c0 + t];
            a[mi][2] = Gu[q0 * G_STR + c0 + t + 4];
            a[mi][3] = Gu[q1 * G_STR + c0 + t + 4];
        }
        const uint32_t* bp = Wu + (8 * wn3 + g) * W_STR + kt * 8 + t;
        uint32_t b0 = bp[0], b1 = bp[4];
        mma8(acc3[0], a[0], b0, b1);
        mma8(acc3[1], a[1], b0, b1);
    }
    __syncthreads();   // P (SD overlay) free

    // epilogue 3: transpose through SMEM, then coalesced stores
    {
        int cc0 = 8 * wn3 + 2 * t;
        float db0 = __ldg(dil_b + cc0);
        float db1 = __ldg(dil_b + cc0 + 1);
        #pragma unroll
        for (int mi = 0; mi < 2; mi++) {
            int jl0 = 32 * wm3 + 16 * mi + g;
            if (jl0 < JC) {
                SD[cc0 * P_STR + jl0]       = acc3[mi][0] + db0;
                SD[(cc0 + 1) * P_STR + jl0] = acc3[mi][1] + db1;
            }
            int jl1 = jl0 + 8;
            if (jl1 < JC) {
                SD[cc0 * P_STR + jl1]       = acc3[mi][2] + db0;
                SD[(cc0 + 1) * P_STR + jl1] = acc3[mi][3] + db1;
            }
        }
    }
    __syncthreads();

    float* outb = out + (size_t)b * CCH * TOUT;
    #pragma unroll
    for (int cc = 0; cc < 4; cc++) {
        int c = 4 * w + cc;
        for (int jl = l; jl < JC; jl += 32) {
            int j = j0 + jl;
            if (j < TOUT) outb[c * TOUT + j] = SD[c * P_STR + jl];
        }
    }
}

extern "C" void kernel_launch(void* const* d_in, const int* in_sizes, int n_in,
                              void* d_out, int out_size)
{
    (void)in_sizes; (void)n_in; (void)out_size;
    const float* x      = (const float*)d_in[0];
    const float* sig_w  = (const float*)d_in[1];
    const float* sig_b  = (const float*)d_in[2];
    const float* gate_w = (const float*)d_in[3];
    const float* gate_b = (const float*)d_in[4];
    const float* out_w  = (const float*)d_in[5];
    const float* out_b  = (const float*)d_in[6];
    const float* skip_w = (const float*)d_in[7];
    const float* skip_b = (const float*)d_in[8];
    const float* dil_w  = (const float*)d_in[9];
    const float* dil_b  = (const float*)d_in[10];
    float* out = (float*)d_out;

    cudaFuncSetAttribute(wavenet_mma_kernel,
                         cudaFuncAttributeMaxDynamicSharedMemorySize, SMEM_BYTES);

    dim3 grid(NCHUNK, BATCH, 1);
    wavenet_mma_kernel<<<grid, NTH, SMEM_BYTES>>>(
        x, sig_w, sig_b, gate_w, gate_b, out_w, out_b,
        skip_w, skip_b, dil_w, dil_b, out);
}

// round 6
// speedup vs baseline: 3.2520x; 1.0385x over previous
#include <cuda_runtime.h>
#include <cstdint>

// Problem constants
#define BATCH 256
#define CCH   64
#define TLEN  4096
#define NBLK  4
#define TOUT  2048
#define JC    60
#define NCHUNK 35
#define NTH   512

// SMEM layout (floats). Strides mod 32 == 4 -> conflict-free fragment loads.
// Multi-use region REG[16896]:
//   during GEMM1:  W1 [n=128][k=128] stride 132
//   after GEMM1:   P  [m=128][h=64]  stride 68  (offset 0,    8704 floats)
//                  W2 [c=64][h=64]   stride 68  (offset 8704, 4352 floats)
//   dilated:       W3 [c=64][k=128]  stride 132 (offset 0,    8448 floats)
//                  SD [c=64][j=60]   stride 68  (offset 8448, 4352 floats)
#define W1_STR 132
#define REG_SZ (128 * W1_STR)            // 16896
#define P_STR  68
#define W2_OFF 8704
#define SD_OFF 8448
#define G_STR  68
#define G_OFF  REG_SZ                     // 16896
#define G_SZ   (129 * G_STR)              // 8772
#define SMEM_FLOATS (G_OFF + G_SZ)        // 25668
#define SMEM_BYTES  (SMEM_FLOATS * 4)     // 102672 -> 2 CTAs/SM

__device__ __forceinline__ uint32_t f2tf(float x) {
    uint32_t r;
    asm("cvt.rna.tf32.f32 %0, %1;" : "=r"(r) : "f"(x));
    return r;
}
__device__ __forceinline__ void mma8(float d[4], const uint32_t a[4],
                                     uint32_t b0, uint32_t b1) {
    asm volatile(
        "mma.sync.aligned.m16n8k8.row.col.f32.tf32.tf32.f32 "
        "{%0,%1,%2,%3}, {%4,%5,%6,%7}, {%8,%9}, {%0,%1,%2,%3};"
        : "+f"(d[0]), "+f"(d[1]), "+f"(d[2]), "+f"(d[3])
        : "r"(a[0]), "r"(a[1]), "r"(a[2]), "r"(a[3]), "r"(b0), "r"(b1));
}

__global__ void __launch_bounds__(NTH, 2)
wavenet_mma_kernel(const float* __restrict__ x,
                   const float* __restrict__ sig_w, const float* __restrict__ sig_b,
                   const float* __restrict__ gate_w, const float* __restrict__ gate_b,
                   const float* __restrict__ out_w, const float* __restrict__ out_b,
                   const float* __restrict__ skip_w, const float* __restrict__ skip_b,
                   const float* __restrict__ dil_w, const float* __restrict__ dil_b,
                   float* __restrict__ out)
{
    extern __shared__ float sm[];
    float*    W1  = sm;                    // during GEMM1 / GEMM3
    uint32_t* W1u = (uint32_t*)W1;
    float*    P   = sm;                    // after GEMM1 (overlay)
    uint32_t* Pu  = (uint32_t*)P;
    float*    W2  = sm + W2_OFF;
    uint32_t* W2u = (uint32_t*)W2;
    float*    SD  = sm + SD_OFF;
    float*    G   = sm + G_OFF;            // G[q][c], q=0..128
    uint32_t* Gu  = (uint32_t*)G;

    const int tid = threadIdx.x;
    const int w   = tid >> 5;
    const int l   = tid & 31;
    const int g   = l >> 2;     // mma group id (0..7)
    const int t   = l & 3;      // thread in group
    const int wm  = w >> 2;     // m-block (rows 32*wm..+32)
    const int wn  = w & 3;      // n-block (cols 32*wn..+32); wn<2 sig, wn>=2 gate

    const int b     = blockIdx.y;
    const int chunk = blockIdx.x;
    const int j0    = chunk * JC;
    const int tbase = 2 * j0 - 5;

    // ---- load x tile into G ----
    const float* xb = x + (size_t)b * CCH * TLEN;
    for (int c = w; c < CCH; c += 16) {
        const float* xc = xb + c * TLEN;
        for (int q = l; q < 129; q += 32) {
            int tt = tbase + q - 1;
            G[q * G_STR + c] = (tt >= 0 && tt < TLEN) ? xc[tt] : 0.f;
        }
    }

    // ================= 4 residual blocks =================
    for (int iblk = 0; iblk < NBLK; iblk++) {
        const float* swp = sig_w  + iblk * 8192;   // [h][c][tap]
        const float* gwp = gate_w + iblk * 8192;
        const float* owp = out_w  + iblk * 4096;   // [c][h]

        // ---- stage W1: rows 0..63 sig, 64..127 gate; k = tap*64 + c ----
        __syncthreads();   // G writes (prev block) / W1 region free
        for (int idx = tid; idx < 8192; idx += NTH) {
            int h = idx >> 7, k = idx & 127;
            int src = h * 128 + (k & 63) * 2 + (k >> 6);
            W1u[h * W1_STR + k]        = f2tf(swp[src]);
            W1u[(h + 64) * W1_STR + k] = f2tf(gwp[src]);
        }
        __syncthreads();

        // ---- GEMM1 (merged): D[128m][128n] ; A[m][tap*64+c] = G[m+tap][c] ----
        float acc[2][4][4];
        #pragma unroll
        for (int mi = 0; mi < 2; mi++)
            #pragma unroll
            for (int ni = 0; ni < 4; ni++)
                #pragma unroll
                for (int q = 0; q < 4; q++) acc[mi][ni][q] = 0.f;

        #pragma unroll
        for (int kt = 0; kt < 16; kt++) {
            const int tap = kt >> 3, c0 = (kt & 7) * 8;
            uint32_t a[2][4];
            #pragma unroll
            for (int mi = 0; mi < 2; mi++) {
                const uint32_t* gp = Gu + (32 * wm + 16 * mi + g + tap) * G_STR + c0 + t;
                a[mi][0] = gp[0];
                a[mi][1] = gp[8 * G_STR];
                a[mi][2] = gp[4];
                a[mi][3] = gp[8 * G_STR + 4];
            }
            #pragma unroll
            for (int ni = 0; ni < 4; ni++) {
                const uint32_t* bp = W1u + (32 * wn + 8 * ni + g) * W1_STR + kt * 8 + t;
                uint32_t b0 = bp[0], b1 = bp[4];
                mma8(acc[0][ni], a[0], b0, b1);
                mma8(acc[1][ni], a[1], b0, b1);
            }
        }
        __syncthreads();   // all W1 reads done -> region becomes P / W2

        // ---- epilogue 1a: gate warps write sigmoid to P; stage W2 ----
        if (wn >= 2) {
            #pragma unroll
            for (int mi = 0; mi < 2; mi++)
                #pragma unroll
                for (int ni = 0; ni < 4; ni++) {
                    int r  = 32 * wm + 16 * mi + g;
                    int gc = 32 * (wn - 2) + 8 * ni + 2 * t;
                    float gb0 = __ldg(gate_b + iblk * 64 + gc);
                    float gb1 = __ldg(gate_b + iblk * 64 + gc + 1);
                    P[r * P_STR + gc]           = 1.f / (1.f + __expf(-(acc[mi][ni][0] + gb0)));
                    P[r * P_STR + gc + 1]       = 1.f / (1.f + __expf(-(acc[mi][ni][1] + gb1)));
                    P[(r + 8) * P_STR + gc]     = 1.f / (1.f + __expf(-(acc[mi][ni][2] + gb0)));
                    P[(r + 8) * P_STR + gc + 1] = 1.f / (1.f + __expf(-(acc[mi][ni][3] + gb1)));
                }
        }
        for (int idx = tid; idx < 4096; idx += NTH) {
            int c = idx >> 6, h = idx & 63;
            W2u[c * P_STR + h] = f2tf(owp[idx]);
        }
        __syncthreads();

        // ---- epilogue 1b: sig warps: p = relu(s+b)*sigmoid -> P (tf32) ----
        if (wn < 2) {
            #pragma unroll
            for (int mi = 0; mi < 2; mi++)
                #pragma unroll
                for (int ni = 0; ni < 4; ni++) {
                    int r  = 32 * wm + 16 * mi + g;
                    int sc = 32 * wn + 8 * ni + 2 * t;
                    float sb0 = __ldg(sig_b + iblk * 64 + sc);
                    float sb1 = __ldg(sig_b + iblk * 64 + sc + 1);
                    float p00 = fmaxf(acc[mi][ni][0] + sb0, 0.f) * P[r * P_STR + sc];
                    float p01 = fmaxf(acc[mi][ni][1] + sb1, 0.f) * P[r * P_STR + sc + 1];
                    float p10 = fmaxf(acc[mi][ni][2] + sb0, 0.f) * P[(r + 8) * P_STR + sc];
                    float p11 = fmaxf(acc[mi][ni][3] + sb1, 0.f) * P[(r + 8) * P_STR + sc + 1];
                    Pu[r * P_STR + sc]           = f2tf(p00);
                    Pu[r * P_STR + sc + 1]       = f2tf(p01);
                    Pu[(r + 8) * P_STR + sc]     = f2tf(p10);
                    Pu[(r + 8) * P_STR + sc + 1] = f2tf(p11);
                }
        }
        __syncthreads();

        // ---- GEMM2: D2[128m][64n] = P x W2^T (K=64); tiles 32m x 16n ----
        {
            const int wn2 = w & 3;   // 16-col blocks
            float acc2[2][2][4];
            #pragma unroll
            for (int mi = 0; mi < 2; mi++)
                #pragma unroll
                for (int ni = 0; ni < 2; ni++)
                    #pragma unroll
                    for (int q = 0; q < 4; q++) acc2[mi][ni][q] = 0.f;

            #pragma unroll
            for (int kt = 0; kt < 8; kt++) {
                uint32_t a[2][4];
                #pragma unroll
                for (int mi = 0; mi < 2; mi++) {
                    const uint32_t* pp = Pu + (32 * wm + 16 * mi + g) * P_STR + kt * 8 + t;
                    a[mi][0] = pp[0];
                    a[mi][1] = pp[8 * P_STR];
                    a[mi][2] = pp[4];
                    a[mi][3] = pp[8 * P_STR + 4];
                }
                #pragma unroll
                for (int ni = 0; ni < 2; ni++) {
                    const uint32_t* bp = W2u + (16 * wn2 + 8 * ni + g) * P_STR + kt * 8 + t;
                    uint32_t b0 = bp[0], b1 = bp[4];
                    mma8(acc2[0][ni], a[0], b0, b1);
                    mma8(acc2[1][ni], a[1], b0, b1);
                }
            }
            // residual update of G
            #pragma unroll
            for (int mi = 0; mi < 2; mi++)
                #pragma unroll
                for (int ni = 0; ni < 2; ni++) {
                    int r0 = 32 * wm + 16 * mi + g;
                    int c0 = 16 * wn2 + 8 * ni + 2 * t;
                    float ob0 = __ldg(out_b + iblk * 64 + c0);
                    float ob1 = __ldg(out_b + iblk * 64 + c0 + 1);
                    float* gp0 = G + (r0 + 1) * G_STR + c0;
                    float* gp1 = G + (r0 + 9) * G_STR + c0;
                    float v00 = acc2[mi][ni][0] + ob0 + gp0[0];
                    float v01 = acc2[mi][ni][1] + ob1 + gp0[1];
                    float v10 = acc2[mi][ni][2] + ob0 + gp1[0];
                    float v11 = acc2[mi][ni][3] + ob1 + gp1[1];
                    if (tbase + r0 < 0)     { v00 = 0.f; v01 = 0.f; }
                    if (tbase + r0 + 8 < 0) { v10 = 0.f; v11 = 0.f; }
                    gp0[0] = v00; gp0[1] = v01;
                    gp1[0] = v10; gp1[1] = v11;
                }
        }
    }
    __syncthreads();

    // ================= skip (last timestep, last chunk only) =================
    if (chunk == NCHUNK - 1 && tid < 64) {
        float acc = __ldg(skip_b + tid);   // t=4095 -> q=21
        #pragma unroll 8
        for (int c = 0; c < 64; c++)
            acc += __ldg(skip_w + tid * 64 + c) * G[21 * G_STR + c];
        out[(size_t)BATCH * CCH * TOUT + b * 64 + tid] = acc;
    }

    // ================= dilated stride-2 conv (GEMM3, M=64) =================
    for (int idx = tid; idx < 8192; idx += NTH) {
        int cc = idx >> 7, k = idx & 127;
        W1u[cc * W1_STR + k] = f2tf(dil_w[cc * 128 + (k & 63) * 2 + (k >> 6)]);
    }
    __syncthreads();

    const int wm3 = w >> 3;   // 0..1 : 32 rows each
    const int wn3 = w & 7;    // 0..7 : 8 cols each
    float acc3[2][4];
    #pragma unroll
    for (int mi = 0; mi < 2; mi++)
        #pragma unroll
        for (int q = 0; q < 4; q++) acc3[mi][q] = 0.f;

    #pragma unroll
    for (int kt = 0; kt < 16; kt++) {
        const int tap = kt >> 3, c0 = (kt & 7) * 8;
        uint32_t a[2][4];
        #pragma unroll
        for (int mi = 0; mi < 2; mi++) {
            int jl = 32 * wm3 + 16 * mi + g;
            int q0 = 2 * jl + 5 + tap;       if (q0 > 128) q0 = 128;
            int q1 = 2 * (jl + 8) + 5 + tap; if (q1 > 128) q1 = 128;
            a[mi][0] = Gu[q0 * G_STR + c0 + t];
            a[mi][1] = Gu[q1 * G_STR + c0 + t];
            a[mi][2] = Gu[q0 * G_STR + c0 + t + 4];
            a[mi][3] = Gu[q1 * G_STR + c0 + t + 4];
        }
        const uint32_t* bp = W1u + (8 * wn3 + g) * W1_STR + kt * 8 + t;
        uint32_t b0 = bp[0], b1 = bp[4];
        mma8(acc3[0], a[0], b0, b1);
        mma8(acc3[1], a[1], b0, b1);
    }

    // epilogue 3: transpose through SD, then coalesced stores
    {
        int cc0 = 8 * wn3 + 2 * t;
        float db0 = __ldg(dil_b + cc0);
        float db1 = __ldg(dil_b + cc0 + 1);
        #pragma unroll
        for (int mi = 0; mi < 2; mi++) {
            int jl0 = 32 * wm3 + 16 * mi + g;
            if (jl0 < JC) {
                SD[cc0 * P_STR + jl0]       = acc3[mi][0] + db0;
                SD[(cc0 + 1) * P_STR + jl0] = acc3[mi][1] + db1;
            }
            int jl1 = jl0 + 8;
            if (jl1 < JC) {
                SD[cc0 * P_STR + jl1]       = acc3[mi][2] + db0;
                SD[(cc0 + 1) * P_STR + jl1] = acc3[mi][3] + db1;
            }
        }
    }
    __syncthreads();

    float* outb = out + (size_t)b * CCH * TOUT;
    #pragma unroll
    for (int cc = 0; cc < 4; cc++) {
        int c = 4 * w + cc;
        for (int jl = l; jl < JC; jl += 32) {
            int j = j0 + jl;
            if (j < TOUT) outb[c * TOUT + j] = SD[c * P_STR + jl];
        }
    }
}

extern "C" void kernel_launch(void* const* d_in, const int* in_sizes, int n_in,
                              void* d_out, int out_size)
{
    (void)in_sizes; (void)n_in; (void)out_size;
    const float* x      = (const float*)d_in[0];
    const float* sig_w  = (const float*)d_in[1];
    const float* sig_b  = (const float*)d_in[2];
    const float* gate_w = (const float*)d_in[3];
    const float* gate_b = (const float*)d_in[4];
    const float* out_w  = (const float*)d_in[5];
    const float* out_b  = (const float*)d_in[6];
    const float* skip_w = (const float*)d_in[7];
    const float* skip_b = (const float*)d_in[8];
    const float* dil_w  = (const float*)d_in[9];
    const float* dil_b  = (const float*)d_in[10];
    float* out = (float*)d_out;

    cudaFuncSetAttribute(wavenet_mma_kernel,
                         cudaFuncAttributeMaxDynamicSharedMemorySize, SMEM_BYTES);

    dim3 grid(NCHUNK, BATCH, 1);
    wavenet_mma_kernel<<<grid, NTH, SMEM_BYTES>>>(
        x, sig_w, sig_b, gate_w, gate_b, out_w, out_b,
        skip_w, skip_b, dil_w, dil_b, out);
}

// round 7
// speedup vs baseline: 4.1012x; 1.2611x over previous
#include <cuda_runtime.h>
#include <cuda_fp16.h>
#include <cstdint>

// Problem constants
#define BATCH 256
#define CCH   64
#define TLEN  4096
#define NBLK  4
#define TOUT  2048
#define JC    60
#define NCHUNK 35
#define NTH   512

// ---- SMEM layout ----
// Multi-use region (bytes 0..34816):
//   GEMM1:  W1 fp16 [n=128][k=128] stride 136 halves (68 words, 68%32==4)
//   GEMM2:  P16 fp16 [m=128][h=64] stride 72 halves at half-off 0
//           W2  fp16 [c=64][h=64]  stride 72 halves at half-off 9216
//   GEMM3:  W3 fp16 [c=64][k=128]  stride 136 halves at half-off 0 (17408 B)
//           SD  fp32 [c=64][j]     stride 68 floats at float-off 4352
// G32 fp32 [129][68] at float-off 8704 (residual master)
// G16 fp16 [129][72] at half-off 34952 (MMA operand mirror)
#define W1_STRH 136
#define W1_STRW 68
#define P_STRH  72
#define P_STRW  36
#define W2_OFFH 9216
#define SD_OFFF 4352
#define SD_STRF 68
#define G32_OFFF 8704
#define G_STRF  68
#define G16_OFFH 34952
#define G16_STRW 36
#define SMEM_BYTES 88480              // 2 CTAs/SM

__device__ __forceinline__ uint32_t packh2(float lo, float hi) {
    __half2 h = __floats2half2_rn(lo, hi);
    return *reinterpret_cast<uint32_t*>(&h);
}
__device__ __forceinline__ void mma16(float d[4], const uint32_t a[4],
                                      uint32_t b0, uint32_t b1) {
    asm volatile(
        "mma.sync.aligned.m16n8k16.row.col.f32.f16.f16.f32 "
        "{%0,%1,%2,%3}, {%4,%5,%6,%7}, {%8,%9}, {%0,%1,%2,%3};"
        : "+f"(d[0]), "+f"(d[1]), "+f"(d[2]), "+f"(d[3])
        : "r"(a[0]), "r"(a[1]), "r"(a[2]), "r"(a[3]), "r"(b0), "r"(b1));
}

__global__ void __launch_bounds__(NTH, 2)
wavenet_h16_kernel(const float* __restrict__ x,
                   const float* __restrict__ sig_w, const float* __restrict__ sig_b,
                   const float* __restrict__ gate_w, const float* __restrict__ gate_b,
                   const float* __restrict__ out_w, const float* __restrict__ out_b,
                   const float* __restrict__ skip_w, const float* __restrict__ skip_b,
                   const float* __restrict__ dil_w, const float* __restrict__ dil_b,
                   float* __restrict__ out)
{
    extern __shared__ float sm[];
    __half*   W1h  = (__half*)sm;
    uint32_t* W1u  = (uint32_t*)sm;
    uint32_t* P16u = (uint32_t*)sm;
    __half*   W2h  = (__half*)sm + W2_OFFH;
    uint32_t* W2u  = (uint32_t*)W2h;
    float*    SD   = sm + SD_OFFF;
    float*    G    = sm + G32_OFFF;
    __half*   G16h = (__half*)sm + G16_OFFH;
    uint32_t* G16u = (uint32_t*)G16h;

    const int tid = threadIdx.x;
    const int w   = tid >> 5;
    const int l   = tid & 31;
    const int g   = l >> 2;     // mma group id (0..7)
    const int t   = l & 3;      // thread in group
    const int wm  = w >> 2;     // m-block (rows 32*wm..+32)
    const int wn  = w & 3;      // n-block (32 cols); wn<2 sig, wn>=2 gate

    const int b     = blockIdx.y;
    const int chunk = blockIdx.x;
    const int j0    = chunk * JC;
    const int tbase = 2 * j0 - 5;

    // ---- load x tile into G (fp32) and G16 (fp16 mirror) ----
    const float* xb = x + (size_t)b * CCH * TLEN;
    for (int c = w; c < CCH; c += 16) {
        const float* xc = xb + c * TLEN;
        for (int q = l; q < 129; q += 32) {
            int tt = tbase + q - 1;
            float v = (tt >= 0 && tt < TLEN) ? xc[tt] : 0.f;
            G[q * G_STRF + c] = v;
            G16h[q * (2 * G16_STRW) + c] = __float2half(v);
        }
    }

    // ================= 4 residual blocks =================
    for (int iblk = 0; iblk < NBLK; iblk++) {
        const float* swp = sig_w  + iblk * 8192;   // [h][c][tap]
        const float* gwp = gate_w + iblk * 8192;
        const float* owp = out_w  + iblk * 4096;   // [c][h]

        // ---- stage W1: rows 0..63 sig, 64..127 gate; k = tap*64 + c ----
        __syncthreads();
        for (int idx = tid; idx < 8192; idx += NTH) {
            int h = idx >> 7, k = idx & 127;
            int src = h * 128 + (k & 63) * 2 + (k >> 6);
            W1h[h * W1_STRH + k]        = __float2half(swp[src]);
            W1h[(h + 64) * W1_STRH + k] = __float2half(gwp[src]);
        }
        __syncthreads();

        // ---- GEMM1: D[128m][128n] ; A[m][tap*64+c] = G16[m+tap][c] ----
        float acc[2][4][4];
        #pragma unroll
        for (int mi = 0; mi < 2; mi++)
            #pragma unroll
            for (int ni = 0; ni < 4; ni++)
                #pragma unroll
                for (int q = 0; q < 4; q++) acc[mi][ni][q] = 0.f;

        #pragma unroll
        for (int kt = 0; kt < 8; kt++) {
            const int tap = kt >> 2, w0 = (kt & 3) * 8;
            uint32_t a[2][4];
            #pragma unroll
            for (int mi = 0; mi < 2; mi++) {
                const uint32_t* gp = G16u + (32 * wm + 16 * mi + g + tap) * G16_STRW + w0 + t;
                a[mi][0] = gp[0];
                a[mi][1] = gp[8 * G16_STRW];
                a[mi][2] = gp[4];
                a[mi][3] = gp[8 * G16_STRW + 4];
            }
            #pragma unroll
            for (int ni = 0; ni < 4; ni++) {
                const uint32_t* bp = W1u + (32 * wn + 8 * ni + g) * W1_STRW + kt * 8 + t;
                uint32_t b0 = bp[0], b1 = bp[4];
                mma16(acc[0][ni], a[0], b0, b1);
                mma16(acc[1][ni], a[1], b0, b1);
            }
        }
        __syncthreads();   // W1 dead -> region becomes P16 / W2

        // ---- epilogue 1a: gate warps write sigmoid pairs to P16; stage W2 ----
        if (wn >= 2) {
            #pragma unroll
            for (int mi = 0; mi < 2; mi++)
                #pragma unroll
                for (int ni = 0; ni < 4; ni++) {
                    int r   = 32 * wm + 16 * mi + g;
                    int gc  = 32 * (wn - 2) + 8 * ni + 2 * t;
                    float gb0 = __ldg(gate_b + iblk * 64 + gc);
                    float gb1 = __ldg(gate_b + iblk * 64 + gc + 1);
                    float s00 = 1.f / (1.f + __expf(-(acc[mi][ni][0] + gb0)));
                    float s01 = 1.f / (1.f + __expf(-(acc[mi][ni][1] + gb1)));
                    float s10 = 1.f / (1.f + __expf(-(acc[mi][ni][2] + gb0)));
                    float s11 = 1.f / (1.f + __expf(-(acc[mi][ni][3] + gb1)));
                    P16u[r * P_STRW + (gc >> 1)]       = packh2(s00, s01);
                    P16u[(r + 8) * P_STRW + (gc >> 1)] = packh2(s10, s11);
                }
        }
        for (int idx = tid; idx < 4096; idx += NTH) {
            int c = idx >> 6, h = idx & 63;
            W2h[c * P_STRH + h] = __float2half(owp[idx]);
        }
        __syncthreads();

        // ---- epilogue 1b: sig warps: p = relu(s+b)*sigmoid -> P16 ----
        if (wn < 2) {
            #pragma unroll
            for (int mi = 0; mi < 2; mi++)
                #pragma unroll
                for (int ni = 0; ni < 4; ni++) {
                    int r  = 32 * wm + 16 * mi + g;
                    int sc = 32 * wn + 8 * ni + 2 * t;
                    float sb0 = __ldg(sig_b + iblk * 64 + sc);
                    float sb1 = __ldg(sig_b + iblk * 64 + sc + 1);
                    uint32_t sw0 = P16u[r * P_STRW + (sc >> 1)];
                    uint32_t sw1 = P16u[(r + 8) * P_STRW + (sc >> 1)];
                    __half2 sg0 = *reinterpret_cast<__half2*>(&sw0);
                    __half2 sg1 = *reinterpret_cast<__half2*>(&sw1);
                    float p00 = fmaxf(acc[mi][ni][0] + sb0, 0.f) * __low2float(sg0);
                    float p01 = fmaxf(acc[mi][ni][1] + sb1, 0.f) * __high2float(sg0);
                    float p10 = fmaxf(acc[mi][ni][2] + sb0, 0.f) * __low2float(sg1);
                    float p11 = fmaxf(acc[mi][ni][3] + sb1, 0.f) * __high2float(sg1);
                    P16u[r * P_STRW + (sc >> 1)]       = packh2(p00, p01);
                    P16u[(r + 8) * P_STRW + (sc >> 1)] = packh2(p10, p11);
                }
        }
        __syncthreads();

        // ---- GEMM2: D2[128m][64n] = P16 x W2^T (K=64); tiles 32m x 16n ----
        {
            const int wn2 = w & 3;
            float acc2[2][2][4];
            #pragma unroll
            for (int mi = 0; mi < 2; mi++)
                #pragma unroll
                for (int ni = 0; ni < 2; ni++)
                    #pragma unroll
                    for (int q = 0; q < 4; q++) acc2[mi][ni][q] = 0.f;

            #pragma unroll
            for (int kt = 0; kt < 4; kt++) {
                uint32_t a[2][4];
                #pragma unroll
                for (int mi = 0; mi < 2; mi++) {
                    const uint32_t* pp = P16u + (32 * wm + 16 * mi + g) * P_STRW + kt * 8 + t;
                    a[mi][0] = pp[0];
                    a[mi][1] = pp[8 * P_STRW];
                    a[mi][2] = pp[4];
                    a[mi][3] = pp[8 * P_STRW + 4];
                }
                #pragma unroll
                for (int ni = 0; ni < 2; ni++) {
                    const uint32_t* bp = W2u + (16 * wn2 + 8 * ni + g) * P_STRW + kt * 8 + t;
                    uint32_t b0 = bp[0], b1 = bp[4];
                    mma16(acc2[0][ni], a[0], b0, b1);
                    mma16(acc2[1][ni], a[1], b0, b1);
                }
            }
            // residual update: G32 + mirror into G16
            #pragma unroll
            for (int mi = 0; mi < 2; mi++)
                #pragma unroll
                for (int ni = 0; ni < 2; ni++) {
                    int r0 = 32 * wm + 16 * mi + g;
                    int c0 = 16 * wn2 + 8 * ni + 2 * t;
                    float ob0 = __ldg(out_b + iblk * 64 + c0);
                    float ob1 = __ldg(out_b + iblk * 64 + c0 + 1);
                    float* gp0 = G + (r0 + 1) * G_STRF + c0;
                    float* gp1 = G + (r0 + 9) * G_STRF + c0;
                    float v00 = acc2[mi][ni][0] + ob0 + gp0[0];
                    float v01 = acc2[mi][ni][1] + ob1 + gp0[1];
                    float v10 = acc2[mi][ni][2] + ob0 + gp1[0];
                    float v11 = acc2[mi][ni][3] + ob1 + gp1[1];
                    if (tbase + r0 < 0)     { v00 = 0.f; v01 = 0.f; }
                    if (tbase + r0 + 8 < 0) { v10 = 0.f; v11 = 0.f; }
                    gp0[0] = v00; gp0[1] = v01;
                    gp1[0] = v10; gp1[1] = v11;
                    G16u[(r0 + 1) * G16_STRW + (c0 >> 1)] = packh2(v00, v01);
                    G16u[(r0 + 9) * G16_STRW + (c0 >> 1)] = packh2(v10, v11);
                }
        }
    }
    __syncthreads();

    // ================= skip (last timestep, last chunk only) =================
    if (chunk == NCHUNK - 1 && tid < 64) {
        float acc = __ldg(skip_b + tid);   // t=4095 -> q=21
        #pragma unroll 8
        for (int c = 0; c < 64; c++)
            acc += __ldg(skip_w + tid * 64 + c) * G[21 * G_STRF + c];
        out[(size_t)BATCH * CCH * TOUT + b * 64 + tid] = acc;
    }

    // ================= dilated stride-2 conv (GEMM3, M=64) =================
    for (int idx = tid; idx < 8192; idx += NTH) {
        int cc = idx >> 7, k = idx & 127;
        W1h[cc * W1_STRH + k] = __float2half(dil_w[cc * 128 + (k & 63) * 2 + (k >> 6)]);
    }
    __syncthreads();

    const int wm3 = w >> 3;   // 0..1 : 32 rows each
    const int wn3 = w & 7;    // 0..7 : 8 cols each
    float acc3[2][4];
    #pragma unroll
    for (int mi = 0; mi < 2; mi++)
        #pragma unroll
        for (int q = 0; q < 4; q++) acc3[mi][q] = 0.f;

    #pragma unroll
    for (int kt = 0; kt < 8; kt++) {
        const int tap = kt >> 2, w0 = (kt & 3) * 8;
        uint32_t a[2][4];
        #pragma unroll
        for (int mi = 0; mi < 2; mi++) {
            int jl = 32 * wm3 + 16 * mi + g;
            int q0 = 2 * jl + 5 + tap;        if (q0 > 128) q0 = 128;
            int q1 = 2 * (jl + 8) + 5 + tap;  if (q1 > 128) q1 = 128;
            a[mi][0] = G16u[q0 * G16_STRW + w0 + t];
            a[mi][1] = G16u[q1 * G16_STRW + w0 + t];
            a[mi][2] = G16u[q0 * G16_STRW + w0 + t + 4];
            a[mi][3] = G16u[q1 * G16_STRW + w0 + t + 4];
        }
        const uint32_t* bp = W1u + (8 * wn3 + g) * W1_STRW + kt * 8 + t;
        uint32_t b0 = bp[0], b1 = bp[4];
        mma16(acc3[0], a[0], b0, b1);
        mma16(acc3[1], a[1], b0, b1);
    }

    // epilogue 3: transpose through SD, then coalesced stores
    {
        int cc0 = 8 * wn3 + 2 * t;
        float db0 = __ldg(dil_b + cc0);
        float db1 = __ldg(dil_b + cc0 + 1);
        #pragma unroll
        for (int mi = 0; mi < 2; mi++) {
            int jl0 = 32 * wm3 + 16 * mi + g;
            if (jl0 < JC) {
                SD[cc0 * SD_STRF + jl0]       = acc3[mi][0] + db0;
                SD[(cc0 + 1) * SD_STRF + jl0] = acc3[mi][1] + db1;
            }
            int jl1 = jl0 + 8;
            if (jl1 < JC) {
                SD[cc0 * SD_STRF + jl1]       = acc3[mi][2] + db0;
                SD[(cc0 + 1) * SD_STRF + jl1] = acc3[mi][3] + db1;
            }
        }
    }
    __syncthreads();

    float* outb = out + (size_t)b * CCH * TOUT;
    #pragma unroll
    for (int cc = 0; cc < 4; cc++) {
        int c = 4 * w + cc;
        for (int jl = l; jl < JC; jl += 32) {
            int j = j0 + jl;
            if (j < TOUT) outb[c * TOUT + j] = SD[c * SD_STRF + jl];
        }
    }
}

extern "C" void kernel_launch(void* const* d_in, const int* in_sizes, int n_in,
                              void* d_out, int out_size)
{
    (void)in_sizes; (void)n_in; (void)out_size;
    const float* x      = (const float*)d_in[0];
    const float* sig_w  = (const float*)d_in[1];
    const float* sig_b  = (const float*)d_in[2];
    const float* gate_w = (const float*)d_in[3];
    const float* gate_b = (const float*)d_in[4];
    const float* out_w  = (const float*)d_in[5];
    const float* out_b  = (const float*)d_in[6];
    const float* skip_w = (const float*)d_in[7];
    const float* skip_b = (const float*)d_in[8];
    const float* dil_w  = (const float*)d_in[9];
    const float* dil_b  = (const float*)d_in[10];
    float* out = (float*)d_out;

    cudaFuncSetAttribute(wavenet_h16_kernel,
                         cudaFuncAttributeMaxDynamicSharedMemorySize, SMEM_BYTES);

    dim3 grid(NCHUNK, BATCH, 1);
    wavenet_h16_kernel<<<grid, NTH, SMEM_BYTES>>>(
        x, sig_w, sig_b, gate_w, gate_b, out_w, out_b,
        skip_w, skip_b, dil_w, dil_b, out);
}

// round 8
// speedup vs baseline: 5.7708x; 1.4071x over previous
#include <cuda_runtime.h>
#include <cuda_fp16.h>
#include <cstdint>

// Problem constants
#define BATCH 256
#define CCH   64
#define TLEN  4096
#define NBLK  4
#define TOUT  2048
#define JC    60
#define NCHUNK 35
#define NTH   512

// ---- SMEM byte layout ----
// REG region [0, 34816): W1 fp16 [128][136] during GEMM1 / W3 fp16 [64][136]
//   during GEMM3 (17408 B) + SD fp32 [64][68] at byte 17408.
//   P16 fp16 [128][72] overlays REG at byte 0 after GEMM1.
// W2 fp16 [64][72] at byte 34816 (9216 B)
// G32 fp32 [129][68] at byte 44032 (35088 B)
// G16 fp16 [129][72] at byte 79120 (18576 B)
#define W1_STRH 136
#define W1_STRW 68
#define P_STRW  36
#define P_STRH  72
#define W2_OFFW 8704
#define SD_OFFF 4352
#define SD_STRF 68
#define G32_OFFF 11008
#define G_STRF  68
#define G16_OFFH 39560
#define G16_OFFW 19780
#define G16_STRW 36
#define G16_STRH 72
#define SMEM_BYTES 97696              // 2 CTAs/SM

// Pre-converted weights (fp16, padded to SMEM strides; zero-init is fine)
__device__ __align__(16) __half wpre1[NBLK][128 * W1_STRH];  // interleaved sig/gate
__device__ __align__(16) __half wpre2[NBLK][64 * P_STRH];    // out_w
__device__ __align__(16) __half wpre3[64 * W1_STRH];         // dil_w

__global__ void __launch_bounds__(256)
prep_weights(const float* __restrict__ sig_w, const float* __restrict__ gate_w,
             const float* __restrict__ out_w, const float* __restrict__ dil_w)
{
    int tid0 = blockIdx.x * 256 + threadIdx.x;
    int nth  = gridDim.x * 256;
    // W1: 4 blocks x 128 rows x 128 k ; row r: wn=r>>5, rr=r&31;
    //   rr<16 -> sig ch 16wn+rr ; else gate ch 16wn+rr-16 ; k = tap*64+c
    for (int idx = tid0; idx < NBLK * 128 * 128; idx += nth) {
        int iblk = idx >> 14, r = (idx >> 7) & 127, k = idx & 127;
        int wn = r >> 5, rr = r & 31;
        int h  = 16 * wn + (rr & 15);
        const float* src = (rr < 16 ? sig_w : gate_w) + iblk * 8192;
        wpre1[iblk][r * W1_STRH + k] = __float2half(src[h * 128 + (k & 63) * 2 + (k >> 6)]);
    }
    // W2: [c][h]
    for (int idx = tid0; idx < NBLK * 64 * 64; idx += nth) {
        int iblk = idx >> 12, c = (idx >> 6) & 63, h = idx & 63;
        wpre2[iblk][c * P_STRH + h] = __float2half(out_w[iblk * 4096 + c * 64 + h]);
    }
    // W3: [cc][k], k = tap*64 + c
    for (int idx = tid0; idx < 64 * 128; idx += nth) {
        int cc = idx >> 7, k = idx & 127;
        wpre3[cc * W1_STRH + k] = __float2half(dil_w[cc * 128 + (k & 63) * 2 + (k >> 6)]);
    }
}

__device__ __forceinline__ uint32_t packh2(float lo, float hi) {
    __half2 h = __floats2half2_rn(lo, hi);
    return *reinterpret_cast<uint32_t*>(&h);
}
__device__ __forceinline__ float sigm(float v) { return 1.f / (1.f + __expf(-v)); }
__device__ __forceinline__ void mma16(float d[4], const uint32_t a[4],
                                      uint32_t b0, uint32_t b1) {
    asm volatile(
        "mma.sync.aligned.m16n8k16.row.col.f32.f16.f16.f32 "
        "{%0,%1,%2,%3}, {%4,%5,%6,%7}, {%8,%9}, {%0,%1,%2,%3};"
        : "+f"(d[0]), "+f"(d[1]), "+f"(d[2]), "+f"(d[3])
        : "r"(a[0]), "r"(a[1]), "r"(a[2]), "r"(a[3]), "r"(b0), "r"(b1));
}

__global__ void __launch_bounds__(NTH, 2)
wavenet_h16_kernel(const float* __restrict__ x,
                   const float* __restrict__ sig_b, const float* __restrict__ gate_b,
                   const float* __restrict__ out_b,
                   const float* __restrict__ skip_w, const float* __restrict__ skip_b,
                   const float* __restrict__ dil_b,
                   float* __restrict__ out)
{
    extern __shared__ float sm[];
    uint4*    REGv = (uint4*)sm;
    uint32_t* W1u  = (uint32_t*)sm;
    uint32_t* P16u = (uint32_t*)sm;
    uint4*    W2v  = (uint4*)((char*)sm + 34816);
    uint32_t* W2u  = (uint32_t*)sm + W2_OFFW;
    float*    SD   = sm + SD_OFFF;
    float*    G    = sm + G32_OFFF;
    __half*   G16h = (__half*)sm + G16_OFFH;
    uint32_t* G16u = (uint32_t*)sm + G16_OFFW;

    const int tid = threadIdx.x;
    const int w   = tid >> 5;
    const int l   = tid & 31;
    const int g   = l >> 2;     // mma group id (0..7)
    const int t   = l & 3;      // thread in group
    const int wm  = w >> 2;     // m-block (rows 32*wm..+32)
    const int wn  = w & 3;      // n-block: channels 16*wn..+16 (sig+gate pair)

    const int b     = blockIdx.y;
    const int chunk = blockIdx.x;
    const int j0    = chunk * JC;
    const int tbase = 2 * j0 - 5;

    // ---- load x tile into G (fp32) and G16 (fp16 mirror) ----
    const float* xb = x + (size_t)b * CCH * TLEN;
    for (int c = w; c < CCH; c += 16) {
        const float* xc = xb + c * TLEN;
        for (int q = l; q < 129; q += 32) {
            int tt = tbase + q - 1;
            float v = (tt >= 0 && tt < TLEN) ? xc[tt] : 0.f;
            G[q * G_STRF + c] = v;
            G16h[q * G16_STRH + c] = __float2half(v);
        }
    }

    // ================= 4 residual blocks =================
    for (int iblk = 0; iblk < NBLK; iblk++) {
        // ---- stage W1 + W2 (pure vector copy; layouts prebuilt) ----
        __syncthreads();   // P16/W2 reads of prev iter done
        {
            const uint4* s1 = (const uint4*)&wpre1[iblk][0];   // 2176 uint4
            for (int idx = tid; idx < 2176; idx += NTH) REGv[idx] = s1[idx];
            const uint4* s2 = (const uint4*)&wpre2[iblk][0];   // 576 uint4
            for (int idx = tid; idx < 576; idx += NTH) W2v[idx] = s2[idx];
        }
        __syncthreads();

        // ---- GEMM1: D[128m][128n] ; A[m][tap*64+c] = G16[m+tap][c] ----
        float acc[2][4][4];
        #pragma unroll
        for (int mi = 0; mi < 2; mi++)
            #pragma unroll
            for (int ni = 0; ni < 4; ni++)
                #pragma unroll
                for (int q = 0; q < 4; q++) acc[mi][ni][q] = 0.f;

        #pragma unroll
        for (int kt = 0; kt < 8; kt++) {
            const int tap = kt >> 2, w0 = (kt & 3) * 8;
            uint32_t a[2][4];
            #pragma unroll
            for (int mi = 0; mi < 2; mi++) {
                const uint32_t* gp = G16u + (32 * wm + 16 * mi + g + tap) * G16_STRW + w0 + t;
                a[mi][0] = gp[0];
                a[mi][1] = gp[8 * G16_STRW];
                a[mi][2] = gp[4];
                a[mi][3] = gp[8 * G16_STRW + 4];
            }
            #pragma unroll
            for (int ni = 0; ni < 4; ni++) {
                const uint32_t* bp = W1u + (32 * wn + 8 * ni + g) * W1_STRW + kt * 8 + t;
                uint32_t b0 = bp[0], b1 = bp[4];
                mma16(acc[0][ni], a[0], b0, b1);
                mma16(acc[1][ni], a[1], b0, b1);
            }
        }
        __syncthreads();   // W1 dead -> region becomes P16

        // ---- epilogue 1 (register-local gating): p = relu(s+b)*sigmoid(g+b) ----
        #pragma unroll
        for (int ni = 0; ni < 2; ni++) {
            int c0 = 16 * wn + 8 * ni + 2 * t;
            float sb0 = __ldg(sig_b  + iblk * 64 + c0);
            float sb1 = __ldg(sig_b  + iblk * 64 + c0 + 1);
            float gb0 = __ldg(gate_b + iblk * 64 + c0);
            float gb1 = __ldg(gate_b + iblk * 64 + c0 + 1);
            #pragma unroll
            for (int mi = 0; mi < 2; mi++) {
                int r = 32 * wm + 16 * mi + g;
                float p00 = fmaxf(acc[mi][ni][0] + sb0, 0.f) * sigm(acc[mi][ni + 2][0] + gb0);
                float p01 = fmaxf(acc[mi][ni][1] + sb1, 0.f) * sigm(acc[mi][ni + 2][1] + gb1);
                float p10 = fmaxf(acc[mi][ni][2] + sb0, 0.f) * sigm(acc[mi][ni + 2][2] + gb0);
                float p11 = fmaxf(acc[mi][ni][3] + sb1, 0.f) * sigm(acc[mi][ni + 2][3] + gb1);
                P16u[r * P_STRW + (c0 >> 1)]       = packh2(p00, p01);
                P16u[(r + 8) * P_STRW + (c0 >> 1)] = packh2(p10, p11);
            }
        }
        __syncthreads();

        // ---- GEMM2: D2[128m][64n] = P16 x W2^T (K=64); tiles 32m x 16n ----
        {
            float acc2[2][2][4];
            #pragma unroll
            for (int mi = 0; mi < 2; mi++)
                #pragma unroll
                for (int ni = 0; ni < 2; ni++)
                    #pragma unroll
                    for (int q = 0; q < 4; q++) acc2[mi][ni][q] = 0.f;

            #pragma unroll
            for (int kt = 0; kt < 4; kt++) {
                uint32_t a[2][4];
                #pragma unroll
                for (int mi = 0; mi < 2; mi++) {
                    const uint32_t* pp = P16u + (32 * wm + 16 * mi + g) * P_STRW + kt * 8 + t;
                    a[mi][0] = pp[0];
                    a[mi][1] = pp[8 * P_STRW];
                    a[mi][2] = pp[4];
                    a[mi][3] = pp[8 * P_STRW + 4];
                }
                #pragma unroll
                for (int ni = 0; ni < 2; ni++) {
                    const uint32_t* bp = W2u + (16 * wn + 8 * ni + g) * P_STRW + kt * 8 + t;
                    uint32_t b0 = bp[0], b1 = bp[4];
                    mma16(acc2[0][ni], a[0], b0, b1);
                    mma16(acc2[1][ni], a[1], b0, b1);
                }
            }
            // residual update: G32 + mirror into G16
            #pragma unroll
            for (int mi = 0; mi < 2; mi++)
                #pragma unroll
                for (int ni = 0; ni < 2; ni++) {
                    int r0 = 32 * wm + 16 * mi + g;
                    int c0 = 16 * wn + 8 * ni + 2 * t;
                    float ob0 = __ldg(out_b + iblk * 64 + c0);
                    float ob1 = __ldg(out_b + iblk * 64 + c0 + 1);
                    float* gp0 = G + (r0 + 1) * G_STRF + c0;
                    float* gp1 = G + (r0 + 9) * G_STRF + c0;
                    float v00 = acc2[mi][ni][0] + ob0 + gp0[0];
                    float v01 = acc2[mi][ni][1] + ob1 + gp0[1];
                    float v10 = acc2[mi][ni][2] + ob0 + gp1[0];
                    float v11 = acc2[mi][ni][3] + ob1 + gp1[1];
                    if (tbase + r0 < 0)     { v00 = 0.f; v01 = 0.f; }
                    if (tbase + r0 + 8 < 0) { v10 = 0.f; v11 = 0.f; }
                    gp0[0] = v00; gp0[1] = v01;
                    gp1[0] = v10; gp1[1] = v11;
                    G16u[(r0 + 1) * G16_STRW + (c0 >> 1)] = packh2(v00, v01);
                    G16u[(r0 + 9) * G16_STRW + (c0 >> 1)] = packh2(v10, v11);
                }
        }
    }
    __syncthreads();

    // ================= skip (last timestep, last chunk only) =================
    if (chunk == NCHUNK - 1 && tid < 64) {
        float acc = __ldg(skip_b + tid);   // t=4095 -> q=21
        #pragma unroll 8
        for (int c = 0; c < 64; c++)
            acc += __ldg(skip_w + tid * 64 + c) * G[21 * G_STRF + c];
        out[(size_t)BATCH * CCH * TOUT + b * 64 + tid] = acc;
    }

    // ================= dilated stride-2 conv (GEMM3, M=64) =================
    {
        const uint4* s3 = (const uint4*)wpre3;   // 1088 uint4
        for (int idx = tid; idx < 1088; idx += NTH) REGv[idx] = s3[idx];
    }
    __syncthreads();

    const int wm3 = w >> 3;   // 0..1 : 32 rows each
    const int wn3 = w & 7;    // 0..7 : 8 cols each
    float acc3[2][4];
    #pragma unroll
    for (int mi = 0; mi < 2; mi++)
        #pragma unroll
        for (int q = 0; q < 4; q++) acc3[mi][q] = 0.f;

    #pragma unroll
    for (int kt = 0; kt < 8; kt++) {
        const int tap = kt >> 2, w0 = (kt & 3) * 8;
        uint32_t a[2][4];
        #pragma unroll
        for (int mi = 0; mi < 2; mi++) {
            int jl = 32 * wm3 + 16 * mi + g;
            int q0 = 2 * jl + 5 + tap;        if (q0 > 128) q0 = 128;
            int q1 = 2 * (jl + 8) + 5 + tap;  if (q1 > 128) q1 = 128;
            a[mi][0] = G16u[q0 * G16_STRW + w0 + t];
            a[mi][1] = G16u[q1 * G16_STRW + w0 + t];
            a[mi][2] = G16u[q0 * G16_STRW + w0 + t + 4];
            a[mi][3] = G16u[q1 * G16_STRW + w0 + t + 4];
        }
        const uint32_t* bp = W1u + (8 * wn3 + g) * W1_STRW + kt * 8 + t;
        uint32_t b0 = bp[0], b1 = bp[4];
        mma16(acc3[0], a[0], b0, b1);
        mma16(acc3[1], a[1], b0, b1);
    }

    // epilogue 3: transpose through SD, then coalesced stores
    {
        int cc0 = 8 * wn3 + 2 * t;
        float db0 = __ldg(dil_b + cc0);
        float db1 = __ldg(dil_b + cc0 + 1);
        #pragma unroll
        for (int mi = 0; mi < 2; mi++) {
            int jl0 = 32 * wm3 + 16 * mi + g;
            if (jl0 < JC) {
                SD[cc0 * SD_STRF + jl0]       = acc3[mi][0] + db0;
                SD[(cc0 + 1) * SD_STRF + jl0] = acc3[mi][1] + db1;
            }
            int jl1 = jl0 + 8;
            if (jl1 < JC) {
                SD[cc0 * SD_STRF + jl1]       = acc3[mi][2] + db0;
                SD[(cc0 + 1) * SD_STRF + jl1] = acc3[mi][3] + db1;
            }
        }
    }
    __syncthreads();

    float* outb = out + (size_t)b * CCH * TOUT;
    #pragma unroll
    for (int cc = 0; cc < 4; cc++) {
        int c = 4 * w + cc;
        for (int jl = l; jl < JC; jl += 32) {
            int j = j0 + jl;
            if (j < TOUT) outb[c * TOUT + j] = SD[c * SD_STRF + jl];
        }
    }
}

extern "C" void kernel_launch(void* const* d_in, const int* in_sizes, int n_in,
                              void* d_out, int out_size)
{
    (void)in_sizes; (void)n_in; (void)out_size;
    const float* x      = (const float*)d_in[0];
    const float* sig_w  = (const float*)d_in[1];
    const float* sig_b  = (const float*)d_in[2];
    const float* gate_w = (const float*)d_in[3];
    const float* gate_b = (const float*)d_in[4];
    const float* out_w  = (const float*)d_in[5];
    const float* out_b  = (const float*)d_in[6];
    const float* skip_w = (const float*)d_in[7];
    const float* skip_b = (const float*)d_in[8];
    const float* dil_w  = (const float*)d_in[9];
    const float* dil_b  = (const float*)d_in[10];
    float* out = (float*)d_out;

    prep_weights<<<96, 256>>>(sig_w, gate_w, out_w, dil_w);

    cudaFuncSetAttribute(wavenet_h16_kernel,
                         cudaFuncAttributeMaxDynamicSharedMemorySize, SMEM_BYTES);
    dim3 grid(NCHUNK, BATCH, 1);
    wavenet_h16_kernel<<<grid, NTH, SMEM_BYTES>>>(
        x, sig_b, gate_b, out_b, skip_w, skip_b, dil_b, out);
}

// round 9
// speedup vs baseline: 5.8882x; 1.0203x over previous
#include <cuda_runtime.h>
#include <cuda_fp16.h>
#include <cstdint>

// Problem constants
#define BATCH 256
#define CCH   64
#define TLEN  4096
#define NBLK  4
#define TOUT  2048
#define JC    60
#define NCHUNK 35
#define NTH   512

// ---- SMEM byte layout ----
// REG region [0, 34816): W1 fp16 [128 rows][272 B] during GEMM1 / W3 fp16
//   [64][272 B] during GEMM3 + SD fp32 [64][68] at byte 17408.
//   P16 fp16 [128][144 B] overlays REG at byte 0 after GEMM1.
// W2 fp16 [64][144 B] at byte 34816
// G32 fp32 [129][68 floats] at byte 44032
// G16 fp16 [129][144 B] at byte 79120
#define W1_STRB 272
#define P_STRB  144
#define P_STRW  36
#define W2_OFFB 34816
#define SD_OFFF 4352
#define SD_STRF 68
#define G32_OFFF 11008
#define G_STRF  68
#define G16_OFFB 79120
#define G16_OFFH 39560
#define G16_STRB 144
#define G16_STRH 72
#define SMEM_BYTES 97696              // 2 CTAs/SM

// Pre-converted fp16 weights, already in SMEM row layout (272B / 144B rows)
__device__ __align__(16) __half wpre1[NBLK][128 * 136];  // sig/gate interleaved
__device__ __align__(16) __half wpre2[NBLK][64 * 72];    // out_w
__device__ __align__(16) __half wpre3[64 * 136];         // dil_w

__global__ void __launch_bounds__(256)
prep_weights(const float* __restrict__ sig_w, const float* __restrict__ gate_w,
             const float* __restrict__ out_w, const float* __restrict__ dil_w)
{
    int tid0 = blockIdx.x * 256 + threadIdx.x;
    int nth  = gridDim.x * 256;
    // W1 row r: wn=r>>5, rr=r&31; rr<16 -> sig ch 16wn+rr else gate; k=tap*64+c
    for (int idx = tid0; idx < NBLK * 128 * 128; idx += nth) {
        int iblk = idx >> 14, r = (idx >> 7) & 127, k = idx & 127;
        int wn = r >> 5, rr = r & 31;
        int h  = 16 * wn + (rr & 15);
        const float* src = (rr < 16 ? sig_w : gate_w) + iblk * 8192;
        wpre1[iblk][r * 136 + k] = __float2half(src[h * 128 + (k & 63) * 2 + (k >> 6)]);
    }
    for (int idx = tid0; idx < NBLK * 64 * 64; idx += nth) {
        int iblk = idx >> 12, c = (idx >> 6) & 63, h = idx & 63;
        wpre2[iblk][c * 72 + h] = __float2half(out_w[iblk * 4096 + c * 64 + h]);
    }
    for (int idx = tid0; idx < 64 * 128; idx += nth) {
        int cc = idx >> 7, k = idx & 127;
        wpre3[cc * 136 + k] = __float2half(dil_w[cc * 128 + (k & 63) * 2 + (k >> 6)]);
    }
}

__device__ __forceinline__ uint32_t packh2(float lo, float hi) {
    __half2 h = __floats2half2_rn(lo, hi);
    return *reinterpret_cast<uint32_t*>(&h);
}
__device__ __forceinline__ float sigm(float v) { return 1.f / (1.f + __expf(-v)); }
__device__ __forceinline__ void mma16(float d[4], const uint32_t a[4],
                                      uint32_t b0, uint32_t b1) {
    asm volatile(
        "mma.sync.aligned.m16n8k16.row.col.f32.f16.f16.f32 "
        "{%0,%1,%2,%3}, {%4,%5,%6,%7}, {%8,%9}, {%0,%1,%2,%3};"
        : "+f"(d[0]), "+f"(d[1]), "+f"(d[2]), "+f"(d[3])
        : "r"(a[0]), "r"(a[1]), "r"(a[2]), "r"(a[3]), "r"(b0), "r"(b1));
}
__device__ __forceinline__ void ldm4(uint32_t r[4], uint32_t addr) {
    asm volatile("ldmatrix.sync.aligned.m8n8.x4.shared.b16 {%0,%1,%2,%3}, [%4];"
        : "=r"(r[0]), "=r"(r[1]), "=r"(r[2]), "=r"(r[3]) : "r"(addr));
}
__device__ __forceinline__ void ldm2(uint32_t& r0, uint32_t& r1, uint32_t addr) {
    asm volatile("ldmatrix.sync.aligned.m8n8.x2.shared.b16 {%0,%1}, [%2];"
        : "=r"(r0), "=r"(r1) : "r"(addr));
}

__global__ void __launch_bounds__(NTH, 2)
wavenet_h16_kernel(const float* __restrict__ x,
                   const float* __restrict__ sig_b, const float* __restrict__ gate_b,
                   const float* __restrict__ out_b,
                   const float* __restrict__ skip_w, const float* __restrict__ skip_b,
                   const float* __restrict__ dil_b,
                   float* __restrict__ out)
{
    extern __shared__ float sm[];
    uint4*    REGv = (uint4*)sm;
    uint32_t* P16u = (uint32_t*)sm;
    uint4*    W2v  = (uint4*)((char*)sm + W2_OFFB);
    float*    SD   = sm + SD_OFFF;
    float*    G    = sm + G32_OFFF;
    __half*   G16h = (__half*)sm + G16_OFFH;
    uint32_t* G16u = (uint32_t*)((char*)sm + G16_OFFB);

    const uint32_t smem_s = (uint32_t)__cvta_generic_to_shared(sm);

    const int tid = threadIdx.x;
    const int w   = tid >> 5;
    const int l   = tid & 31;
    const int g   = l >> 2;        // mma group id (0..7)
    const int t   = l & 3;         // thread in group
    const int wm  = w >> 2;        // m-block (rows 32*wm..+32)
    const int wn  = w & 3;         // n-block: channels 16*wn..+16 (sig+gate)
    const int matLo = (l >> 3) & 1;   // ldmatrix lane decomposition
    const int matHi = l >> 4;
    const int lmrow = l & 7;

    const int b     = blockIdx.y;
    const int chunk = blockIdx.x;
    const int j0    = chunk * JC;
    const int tbase = 2 * j0 - 5;

    // ---- load x tile into G (fp32) and G16 (fp16 mirror) ----
    const float* xb = x + (size_t)b * CCH * TLEN;
    for (int c = w; c < CCH; c += 16) {
        const float* xc = xb + c * TLEN;
        for (int q = l; q < 129; q += 32) {
            int tt = tbase + q - 1;
            float v = (tt >= 0 && tt < TLEN) ? xc[tt] : 0.f;
            G[q * G_STRF + c] = v;
            G16h[q * G16_STRH + c] = __float2half(v);
        }
    }

    // ldmatrix base addresses (per-lane)
    // GEMM1 A (G16): mat0/1 -> m rows +0/+8 (k0), mat2/3 -> k+8
    uint32_t aAdr1[2];
    #pragma unroll
    for (int mi = 0; mi < 2; mi++)
        aAdr1[mi] = smem_s + G16_OFFB
                  + (32 * wm + 16 * mi + matLo * 8 + lmrow) * G16_STRB + matHi * 16;
    // GEMM1 B (W1): pairs p: mat0=(ni=2p,k0) mat1=(ni=2p,k8) mat2=(ni=2p+1,k0) mat3=(.. ,k8)
    uint32_t bAdr1[2];
    #pragma unroll
    for (int p = 0; p < 2; p++)
        bAdr1[p] = smem_s + (32 * wn + 16 * p + matHi * 8 + lmrow) * W1_STRB + matLo * 16;
    // GEMM2 A (P16) / B (W2)
    const uint32_t aAdr2base = smem_s + (32 * wm + matLo * 8 + lmrow) * P_STRB + matHi * 16;
    const uint32_t bAdr2 = smem_s + W2_OFFB + (16 * wn + matHi * 8 + lmrow) * P_STRB + matLo * 16;

    // ================= 4 residual blocks =================
    for (int iblk = 0; iblk < NBLK; iblk++) {
        // ---- stage W1 + W2 (pure vector copy; layouts prebuilt) ----
        __syncthreads();
        {
            const uint4* s1 = (const uint4*)&wpre1[iblk][0];   // 2176 uint4
            for (int idx = tid; idx < 2176; idx += NTH) REGv[idx] = s1[idx];
            const uint4* s2 = (const uint4*)&wpre2[iblk][0];   // 576 uint4
            for (int idx = tid; idx < 576; idx += NTH) W2v[idx] = s2[idx];
        }
        __syncthreads();

        // ---- GEMM1: D[128m][128n] ; A[m][tap*64+c] = G16[m+tap][c] ----
        float acc[2][4][4];
        #pragma unroll
        for (int mi = 0; mi < 2; mi++)
            #pragma unroll
            for (int ni = 0; ni < 4; ni++)
                #pragma unroll
                for (int q = 0; q < 4; q++) acc[mi][ni][q] = 0.f;

        #pragma unroll
        for (int kt = 0; kt < 8; kt++) {
            const uint32_t kOffA = (kt >> 2) * G16_STRB + (kt & 3) * 32;
            const uint32_t kOffB = kt * 32;
            uint32_t a0[4], a1[4], bb[4];
            ldm4(a0, aAdr1[0] + kOffA);
            ldm4(a1, aAdr1[1] + kOffA);
            ldm4(bb, bAdr1[0] + kOffB);
            mma16(acc[0][0], a0, bb[0], bb[1]);
            mma16(acc[1][0], a1, bb[0], bb[1]);
            mma16(acc[0][1], a0, bb[2], bb[3]);
            mma16(acc[1][1], a1, bb[2], bb[3]);
            ldm4(bb, bAdr1[1] + kOffB);
            mma16(acc[0][2], a0, bb[0], bb[1]);
            mma16(acc[1][2], a1, bb[0], bb[1]);
            mma16(acc[0][3], a0, bb[2], bb[3]);
            mma16(acc[1][3], a1, bb[2], bb[3]);
        }
        __syncthreads();   // W1 dead -> region becomes P16

        // ---- epilogue 1 (register-local gating): p = relu(s+b)*sigmoid(g+b) ----
        #pragma unroll
        for (int ni = 0; ni < 2; ni++) {
            int c0 = 16 * wn + 8 * ni + 2 * t;
            float sb0 = __ldg(sig_b  + iblk * 64 + c0);
            float sb1 = __ldg(sig_b  + iblk * 64 + c0 + 1);
            float gb0 = __ldg(gate_b + iblk * 64 + c0);
            float gb1 = __ldg(gate_b + iblk * 64 + c0 + 1);
            #pragma unroll
            for (int mi = 0; mi < 2; mi++) {
                int r = 32 * wm + 16 * mi + g;
                float p00 = fmaxf(acc[mi][ni][0] + sb0, 0.f) * sigm(acc[mi][ni + 2][0] + gb0);
                float p01 = fmaxf(acc[mi][ni][1] + sb1, 0.f) * sigm(acc[mi][ni + 2][1] + gb1);
                float p10 = fmaxf(acc[mi][ni][2] + sb0, 0.f) * sigm(acc[mi][ni + 2][2] + gb0);
                float p11 = fmaxf(acc[mi][ni][3] + sb1, 0.f) * sigm(acc[mi][ni + 2][3] + gb1);
                P16u[r * P_STRW + (c0 >> 1)]       = packh2(p00, p01);
                P16u[(r + 8) * P_STRW + (c0 >> 1)] = packh2(p10, p11);
            }
        }
        __syncthreads();

        // ---- GEMM2: D2[128m][64n] = P16 x W2^T (K=64); tiles 32m x 16n ----
        {
            float acc2[2][2][4];
            #pragma unroll
            for (int mi = 0; mi < 2; mi++)
                #pragma unroll
                for (int ni = 0; ni < 2; ni++)
                    #pragma unroll
                    for (int q = 0; q < 4; q++) acc2[mi][ni][q] = 0.f;

            #pragma unroll
            for (int kt = 0; kt < 4; kt++) {
                uint32_t a0[4], a1[4], bb[4];
                ldm4(a0, aAdr2base + kt * 32);
                ldm4(a1, aAdr2base + 16 * P_STRB + kt * 32);
                ldm4(bb, bAdr2 + kt * 32);
                mma16(acc2[0][0], a0, bb[0], bb[1]);
                mma16(acc2[1][0], a1, bb[0], bb[1]);
                mma16(acc2[0][1], a0, bb[2], bb[3]);
                mma16(acc2[1][1], a1, bb[2], bb[3]);
            }
            // residual update: G32 + mirror into G16
            #pragma unroll
            for (int mi = 0; mi < 2; mi++)
                #pragma unroll
                for (int ni = 0; ni < 2; ni++) {
                    int r0 = 32 * wm + 16 * mi + g;
                    int c0 = 16 * wn + 8 * ni + 2 * t;
                    float ob0 = __ldg(out_b + iblk * 64 + c0);
                    float ob1 = __ldg(out_b + iblk * 64 + c0 + 1);
                    float* gp0 = G + (r0 + 1) * G_STRF + c0;
                    float* gp1 = G + (r0 + 9) * G_STRF + c0;
                    float v00 = acc2[mi][ni][0] + ob0 + gp0[0];
                    float v01 = acc2[mi][ni][1] + ob1 + gp0[1];
                    float v10 = acc2[mi][ni][2] + ob0 + gp1[0];
                    float v11 = acc2[mi][ni][3] + ob1 + gp1[1];
                    if (tbase + r0 < 0)     { v00 = 0.f; v01 = 0.f; }
                    if (tbase + r0 + 8 < 0) { v10 = 0.f; v11 = 0.f; }
                    gp0[0] = v00; gp0[1] = v01;
                    gp1[0] = v10; gp1[1] = v11;
                    G16u[(r0 + 1) * P_STRW + (c0 >> 1)] = packh2(v00, v01);
                    G16u[(r0 + 9) * P_STRW + (c0 >> 1)] = packh2(v10, v11);
                }
        }
    }
    __syncthreads();

    // ================= skip (last timestep, last chunk only) =================
    if (chunk == NCHUNK - 1 && tid < 64) {
        float acc = __ldg(skip_b + tid);   // t=4095 -> q=21
        #pragma unroll 8
        for (int c = 0; c < 64; c++)
            acc += __ldg(skip_w + tid * 64 + c) * G[21 * G_STRF + c];
        out[(size_t)BATCH * CCH * TOUT + b * 64 + tid] = acc;
    }

    // ================= dilated stride-2 conv (GEMM3, M=64) =================
    {
        const uint4* s3 = (const uint4*)wpre3;   // 1088 uint4
        for (int idx = tid; idx < 1088; idx += NTH) REGv[idx] = s3[idx];
    }
    __syncthreads();

    const int wm3 = w >> 3;   // 0..1 : 32 rows each
    const int wn3 = w & 7;    // 0..7 : 8 cols each
    const uint32_t bAdr3 = smem_s + (8 * wn3 + lmrow) * W1_STRB + matLo * 16;
    float acc3[2][4];
    #pragma unroll
    for (int mi = 0; mi < 2; mi++)
        #pragma unroll
        for (int q = 0; q < 4; q++) acc3[mi][q] = 0.f;

    #pragma unroll
    for (int kt = 0; kt < 8; kt++) {
        const int tap = kt >> 2;
        uint32_t a0[4], a1[4], b0, b1;
        #pragma unroll
        for (int mi = 0; mi < 2; mi++) {
            int jl = 32 * wm3 + 16 * mi + matLo * 8 + lmrow;
            int q  = 2 * jl + 5 + tap;
            if (q > 128) q = 128;
            uint32_t addr = smem_s + G16_OFFB + q * G16_STRB + matHi * 16 + (kt & 3) * 32;
            if (mi == 0) ldm4(a0, addr); else ldm4(a1, addr);
        }
        ldm2(b0, b1, bAdr3 + kt * 32);
        mma16(acc3[0], a0, b0, b1);
        mma16(acc3[1], a1, b0, b1);
    }

    // epilogue 3: transpose through SD, then coalesced stores
    {
        int cc0 = 8 * wn3 + 2 * t;
        float db0 = __ldg(dil_b + cc0);
        float db1 = __ldg(dil_b + cc0 + 1);
        #pragma unroll
        for (int mi = 0; mi < 2; mi++) {
            int jl0 = 32 * wm3 + 16 * mi + g;
            if (jl0 < JC) {
                SD[cc0 * SD_STRF + jl0]       = acc3[mi][0] + db0;
                SD[(cc0 + 1) * SD_STRF + jl0] = acc3[mi][1] + db1;
            }
            int jl1 = jl0 + 8;
            if (jl1 < JC) {
                SD[cc0 * SD_STRF + jl1]       = acc3[mi][2] + db0;
                SD[(cc0 + 1) * SD_STRF + jl1] = acc3[mi][3] + db1;
            }
        }
    }
    __syncthreads();

    float* outb = out + (size_t)b * CCH * TOUT;
    #pragma unroll
    for (int cc = 0; cc < 4; cc++) {
        int c = 4 * w + cc;
        for (int jl = l; jl < JC; jl += 32) {
            int j = j0 + jl;
            if (j < TOUT) outb[c * TOUT + j] = SD[c * SD_STRF + jl];
        }
    }
}

extern "C" void kernel_launch(void* const* d_in, const int* in_sizes, int n_in,
                              void* d_out, int out_size)
{
    (void)in_sizes; (void)n_in; (void)out_size;
    const float* x      = (const float*)d_in[0];
    const float* sig_w  = (const float*)d_in[1];
    const float* sig_b  = (const float*)d_in[2];
    const float* gate_w = (const float*)d_in[3];
    const float* gate_b = (const float*)d_in[4];
    const float* out_w  = (const float*)d_in[5];
    const float* out_b  = (const float*)d_in[6];
    const float* skip_w = (const float*)d_in[7];
    const float* skip_b = (const float*)d_in[8];
    const float* dil_w  = (const float*)d_in[9];
    const float* dil_b  = (const float*)d_in[10];
    float* out = (float*)d_out;

    prep_weights<<<96, 256>>>(sig_w, gate_w, out_w, dil_w);

    cudaFuncSetAttribute(wavenet_h16_kernel,
                         cudaFuncAttributeMaxDynamicSharedMemorySize, SMEM_BYTES);
    dim3 grid(NCHUNK, BATCH, 1);
    wavenet_h16_kernel<<<grid, NTH, SMEM_BYTES>>>(
        x, sig_b, gate_b, out_b, skip_w, skip_b, dil_b, out);
}

// round 10
// speedup vs baseline: 6.7207x; 1.1414x over previous
#include <cuda_runtime.h>
#include <cuda_fp16.h>
#include <cstdint>

// Problem constants
#define BATCH 256
#define CCH   64
#define TLEN  4096
#define NBLK  4
#define TOUT  2048
#define JC    60
#define NCHUNK 35
#define NTH   512

// ---- SMEM byte layout ----
// REG region [0, 34816): W1 fp16 [128][272B] during GEMM1 / W3 fp16 [64][272B]
//   during GEMM3 + SD fp32 [64][68f] at byte 17408.
//   P16 fp16 [128][144B] overlays REG after GEMM1.
// W2 fp16 [64][144B] at byte 34816
// G32 fp32 [129][68f] at byte 44032 ; GD16 fp16 [64][272B] overlays it (dilated)
// G16 fp16 [129][144B] at byte 79120
#define W1_STRB 272
#define P_STRB  144
#define P_STRW  36
#define W2_OFFB 34816
#define SD_OFFF 4352
#define SD_STRF 68
#define G32_OFFF 11008
#define G_STRF  68
#define GD_OFFB 44032
#define GD_STRW 68
#define G16_OFFB 79120
#define G16_OFFH 39560
#define G16_STRB 144
#define G16_STRH 72
#define SMEM_BYTES 97696              // 2 CTAs/SM

// Pre-converted fp16 weights, already in SMEM row layout (272B / 144B rows)
__device__ __align__(16) __half wpre1[NBLK][128 * 136];  // sig/gate interleaved
__device__ __align__(16) __half wpre2[NBLK][64 * 72];    // out_w
__device__ __align__(16) __half wpre3[64 * 136];         // dil_w

__global__ void __launch_bounds__(256)
prep_weights(const float* __restrict__ sig_w, const float* __restrict__ gate_w,
             const float* __restrict__ out_w, const float* __restrict__ dil_w)
{
    int tid0 = blockIdx.x * 256 + threadIdx.x;
    int nth  = gridDim.x * 256;
    for (int idx = tid0; idx < NBLK * 128 * 128; idx += nth) {
        int iblk = idx >> 14, r = (idx >> 7) & 127, k = idx & 127;
        int wn = r >> 5, rr = r & 31;
        int h  = 16 * wn + (rr & 15);
        const float* src = (rr < 16 ? sig_w : gate_w) + iblk * 8192;
        wpre1[iblk][r * 136 + k] = __float2half(src[h * 128 + (k & 63) * 2 + (k >> 6)]);
    }
    for (int idx = tid0; idx < NBLK * 64 * 64; idx += nth) {
        int iblk = idx >> 12, c = (idx >> 6) & 63, h = idx & 63;
        wpre2[iblk][c * 72 + h] = __float2half(out_w[iblk * 4096 + c * 64 + h]);
    }
    for (int idx = tid0; idx < 64 * 128; idx += nth) {
        int cc = idx >> 7, k = idx & 127;
        wpre3[cc * 136 + k] = __float2half(dil_w[cc * 128 + (k & 63) * 2 + (k >> 6)]);
    }
}

__device__ __forceinline__ uint32_t packh2(float lo, float hi) {
    __half2 h = __floats2half2_rn(lo, hi);
    return *reinterpret_cast<uint32_t*>(&h);
}
__device__ __forceinline__ float sigm(float v) { return 1.f / (1.f + __expf(-v)); }
__device__ __forceinline__ void mma16(float d[4], const uint32_t a[4],
                                      uint32_t b0, uint32_t b1) {
    asm volatile(
        "mma.sync.aligned.m16n8k16.row.col.f32.f16.f16.f32 "
        "{%0,%1,%2,%3}, {%4,%5,%6,%7}, {%8,%9}, {%0,%1,%2,%3};"
        : "+f"(d[0]), "+f"(d[1]), "+f"(d[2]), "+f"(d[3])
        : "r"(a[0]), "r"(a[1]), "r"(a[2]), "r"(a[3]), "r"(b0), "r"(b1));
}
__device__ __forceinline__ void ldm4(uint32_t r[4], uint32_t addr) {
    asm volatile("ldmatrix.sync.aligned.m8n8.x4.shared.b16 {%0,%1,%2,%3}, [%4];"
        : "=r"(r[0]), "=r"(r[1]), "=r"(r[2]), "=r"(r[3]) : "r"(addr));
}
__device__ __forceinline__ void ldm2(uint32_t& r0, uint32_t& r1, uint32_t addr) {
    asm volatile("ldmatrix.sync.aligned.m8n8.x2.shared.b16 {%0,%1}, [%2];"
        : "=r"(r0), "=r"(r1) : "r"(addr));
}
__device__ __forceinline__ void cp16(uint32_t dst, const __half* src) {
    asm volatile("cp.async.cg.shared.global [%0], [%1], 16;"
        :: "r"(dst), "l"(__cvta_generic_to_global(src)));
}
#define CP_COMMIT() asm volatile("cp.async.commit_group;" ::: "memory")
#define CP_WAIT0()  asm volatile("cp.async.wait_group 0;" ::: "memory")

__global__ void __launch_bounds__(NTH, 2)
wavenet_h16_kernel(const float* __restrict__ x,
                   const float* __restrict__ sig_b, const float* __restrict__ gate_b,
                   const float* __restrict__ out_b,
                   const float* __restrict__ skip_w, const float* __restrict__ skip_b,
                   const float* __restrict__ dil_b,
                   float* __restrict__ out)
{
    extern __shared__ float sm[];
    uint32_t* P16u = (uint32_t*)sm;
    float*    SD   = sm + SD_OFFF;
    float*    G    = sm + G32_OFFF;
    uint32_t* GDu  = (uint32_t*)((char*)sm + GD_OFFB);
    __half*   G16h = (__half*)sm + G16_OFFH;
    uint32_t* G16u = (uint32_t*)((char*)sm + G16_OFFB);

    const uint32_t smem_s = (uint32_t)__cvta_generic_to_shared(sm);

    const int tid = threadIdx.x;
    const int w   = tid >> 5;
    const int l   = tid & 31;
    const int g   = l >> 2;
    const int t   = l & 3;
    const int wm  = w >> 2;
    const int wn  = w & 3;
    const int matLo = (l >> 3) & 1;
    const int matHi = l >> 4;
    const int lmrow = l & 7;

    const int b     = blockIdx.y;
    const int chunk = blockIdx.x;
    const int j0    = chunk * JC;
    const int tbase = 2 * j0 - 5;

    // ---- prologue: stage W1(0)+W2(0) via cp.async, overlapped with x-load ----
    for (int idx = tid; idx < 2176; idx += NTH)
        cp16(smem_s + idx * 16, &wpre1[0][0] + idx * 8);
    for (int idx = tid; idx < 576; idx += NTH)
        cp16(smem_s + W2_OFFB + idx * 16, &wpre2[0][0] + idx * 8);
    CP_COMMIT();

    // ---- load x tile into G (fp32) and G16 (fp16 mirror) ----
    const float* xb = x + (size_t)b * CCH * TLEN;
    for (int c = w; c < CCH; c += 16) {
        const float* xc = xb + c * TLEN;
        for (int q = l; q < 129; q += 32) {
            int tt = tbase + q - 1;
            float v = (tt >= 0 && tt < TLEN) ? xc[tt] : 0.f;
            G[q * G_STRF + c] = v;
            G16h[q * G16_STRH + c] = __float2half(v);
        }
    }
    CP_WAIT0();
    __syncthreads();

    // ldmatrix base addresses
    uint32_t aAdr1[2];
    #pragma unroll
    for (int mi = 0; mi < 2; mi++)
        aAdr1[mi] = smem_s + G16_OFFB
                  + (32 * wm + 16 * mi + matLo * 8 + lmrow) * G16_STRB + matHi * 16;
    uint32_t bAdr1[2];
    #pragma unroll
    for (int p = 0; p < 2; p++)
        bAdr1[p] = smem_s + (32 * wn + 16 * p + matHi * 8 + lmrow) * W1_STRB + matLo * 16;
    const uint32_t aAdr2base = smem_s + (32 * wm + matLo * 8 + lmrow) * P_STRB + matHi * 16;
    const uint32_t bAdr2 = smem_s + W2_OFFB + (16 * wn + matHi * 8 + lmrow) * P_STRB + matLo * 16;

    // ================= 4 residual blocks =================
    for (int iblk = 0; iblk < NBLK; iblk++) {
        // ---- GEMM1: D[128m][128n] ; A[m][tap*64+c] = G16[m+tap][c] ----
        float acc[2][4][4];
        #pragma unroll
        for (int mi = 0; mi < 2; mi++)
            #pragma unroll
            for (int ni = 0; ni < 4; ni++)
                #pragma unroll
                for (int q = 0; q < 4; q++) acc[mi][ni][q] = 0.f;

        #pragma unroll
        for (int kt = 0; kt < 8; kt++) {
            const uint32_t kOffA = (kt >> 2) * G16_STRB + (kt & 3) * 32;
            const uint32_t kOffB = kt * 32;
            uint32_t a0[4], a1[4], bb[4];
            ldm4(a0, aAdr1[0] + kOffA);
            ldm4(a1, aAdr1[1] + kOffA);
            ldm4(bb, bAdr1[0] + kOffB);
            mma16(acc[0][0], a0, bb[0], bb[1]);
            mma16(acc[1][0], a1, bb[0], bb[1]);
            mma16(acc[0][1], a0, bb[2], bb[3]);
            mma16(acc[1][1], a1, bb[2], bb[3]);
            ldm4(bb, bAdr1[1] + kOffB);
            mma16(acc[0][2], a0, bb[0], bb[1]);
            mma16(acc[1][2], a1, bb[0], bb[1]);
            mma16(acc[0][3], a0, bb[2], bb[3]);
            mma16(acc[1][3], a1, bb[2], bb[3]);
        }
        __syncthreads();   // W1 dead -> region becomes P16

        // ---- epilogue 1 (register-local gating) ----
        #pragma unroll
        for (int ni = 0; ni < 2; ni++) {
            int c0 = 16 * wn + 8 * ni + 2 * t;
            float sb0 = __ldg(sig_b  + iblk * 64 + c0);
            float sb1 = __ldg(sig_b  + iblk * 64 + c0 + 1);
            float gb0 = __ldg(gate_b + iblk * 64 + c0);
            float gb1 = __ldg(gate_b + iblk * 64 + c0 + 1);
            #pragma unroll
            for (int mi = 0; mi < 2; mi++) {
                int r = 32 * wm + 16 * mi + g;
                float p00 = fmaxf(acc[mi][ni][0] + sb0, 0.f) * sigm(acc[mi][ni + 2][0] + gb0);
                float p01 = fmaxf(acc[mi][ni][1] + sb1, 0.f) * sigm(acc[mi][ni + 2][1] + gb1);
                float p10 = fmaxf(acc[mi][ni][2] + sb0, 0.f) * sigm(acc[mi][ni + 2][2] + gb0);
                float p11 = fmaxf(acc[mi][ni][3] + sb1, 0.f) * sigm(acc[mi][ni + 2][3] + gb1);
                P16u[r * P_STRW + (c0 >> 1)]       = packh2(p00, p01);
                P16u[(r + 8) * P_STRW + (c0 >> 1)] = packh2(p10, p11);
            }
        }
        __syncthreads();

        // ---- GEMM2: D2[128m][64n] = P16 x W2^T ----
        float acc2[2][2][4];
        #pragma unroll
        for (int mi = 0; mi < 2; mi++)
            #pragma unroll
            for (int ni = 0; ni < 2; ni++)
                #pragma unroll
                for (int q = 0; q < 4; q++) acc2[mi][ni][q] = 0.f;

        #pragma unroll
        for (int kt = 0; kt < 4; kt++) {
            uint32_t a0[4], a1[4], bb[4];
            ldm4(a0, aAdr2base + kt * 32);
            ldm4(a1, aAdr2base + 16 * P_STRB + kt * 32);
            ldm4(bb, bAdr2 + kt * 32);
            mma16(acc2[0][0], a0, bb[0], bb[1]);
            mma16(acc2[1][0], a1, bb[0], bb[1]);
            mma16(acc2[0][1], a0, bb[2], bb[3]);
            mma16(acc2[1][1], a1, bb[2], bb[3]);
        }
        __syncthreads();   // P16 / W2 dead -> stage next weights async

        if (iblk + 1 < NBLK) {
            for (int idx = tid; idx < 2176; idx += NTH)
                cp16(smem_s + idx * 16, &wpre1[iblk + 1][0] + idx * 8);
            for (int idx = tid; idx < 576; idx += NTH)
                cp16(smem_s + W2_OFFB + idx * 16, &wpre2[iblk + 1][0] + idx * 8);
        } else {
            for (int idx = tid; idx < 1088; idx += NTH)
                cp16(smem_s + idx * 16, wpre3 + idx * 8);
        }
        CP_COMMIT();

        // ---- epilogue 2: residual update (overlapped with cp.async) ----
        const float* obp = out_b + iblk * 64;
        #pragma unroll
        for (int mi = 0; mi < 2; mi++)
            #pragma unroll
            for (int ni = 0; ni < 2; ni++) {
                int r0 = 32 * wm + 16 * mi + g;
                int c0 = 16 * wn + 8 * ni + 2 * t;
                float ob0 = __ldg(obp + c0);
                float ob1 = __ldg(obp + c0 + 1);
                float2* gp0 = (float2*)(G + (r0 + 1) * G_STRF + c0);
                float2* gp1 = (float2*)(G + (r0 + 9) * G_STRF + c0);
                float2 o0 = *gp0, o1 = *gp1;
                float v00 = acc2[mi][ni][0] + ob0 + o0.x;
                float v01 = acc2[mi][ni][1] + ob1 + o0.y;
                float v10 = acc2[mi][ni][2] + ob0 + o1.x;
                float v11 = acc2[mi][ni][3] + ob1 + o1.y;
                if (tbase + r0 < 0)     { v00 = 0.f; v01 = 0.f; }
                if (tbase + r0 + 8 < 0) { v10 = 0.f; v11 = 0.f; }
                *gp0 = make_float2(v00, v01);
                *gp1 = make_float2(v10, v11);
                G16u[(r0 + 1) * P_STRW + (c0 >> 1)] = packh2(v00, v01);
                G16u[(r0 + 9) * P_STRW + (c0 >> 1)] = packh2(v10, v11);
            }
        CP_WAIT0();
        __syncthreads();
    }

    // ================= skip (last timestep, last chunk only) =================
    if (chunk == NCHUNK - 1 && tid < 64) {
        float acc = __ldg(skip_b + tid);   // t=4095 -> q=21
        #pragma unroll 8
        for (int c = 0; c < 64; c++)
            acc += __ldg(skip_w + tid * 64 + c) * G[21 * G_STRF + c];
        out[(size_t)BATCH * CCH * TOUT + b * 64 + tid] = acc;
    }
    __syncthreads();   // skip's G32 reads done before GD overlays it

    // ---- GD gather: GD[jl][tap*64+c] = G16[2jl+5+tap][c], 272B rows ----
    for (int idx = tid; idx < 4096; idx += NTH) {
        int jl = idx >> 6, kw = idx & 63;
        int tap = kw >> 5, cw = kw & 31;
        int q = 2 * jl + 5 + tap;
        if (q > 128) q = 128;
        GDu[jl * GD_STRW + kw] = G16u[q * P_STRW + cw];
    }
    __syncthreads();

    // ================= dilated stride-2 conv (GEMM3, M=64) =================
    const int wm3 = w >> 3;
    const int wn3 = w & 7;
    const uint32_t bAdr3 = smem_s + (8 * wn3 + lmrow) * W1_STRB + matLo * 16;
    uint32_t aAdr3[2];
    #pragma unroll
    for (int mi = 0; mi < 2; mi++)
        aAdr3[mi] = smem_s + GD_OFFB
                  + (32 * wm3 + 16 * mi + matLo * 8 + lmrow) * W1_STRB + matHi * 16;

    float acc3[2][4];
    #pragma unroll
    for (int mi = 0; mi < 2; mi++)
        #pragma unroll
        for (int q = 0; q < 4; q++) acc3[mi][q] = 0.f;

    #pragma unroll
    for (int kt = 0; kt < 8; kt++) {
        uint32_t a0[4], a1[4], b0, b1;
        ldm4(a0, aAdr3[0] + kt * 32);
        ldm4(a1, aAdr3[1] + kt * 32);
        ldm2(b0, b1, bAdr3 + kt * 32);
        mma16(acc3[0], a0, b0, b1);
        mma16(acc3[1], a1, b0, b1);
    }

    // epilogue 3: transpose through SD, then coalesced stores
    {
        int cc0 = 8 * wn3 + 2 * t;
        float db0 = __ldg(dil_b + cc0);
        float db1 = __ldg(dil_b + cc0 + 1);
        #pragma unroll
        for (int mi = 0; mi < 2; mi++) {
            int jl0 = 32 * wm3 + 16 * mi + g;
            if (jl0 < JC) {
                SD[cc0 * SD_STRF + jl0]       = acc3[mi][0] + db0;
                SD[(cc0 + 1) * SD_STRF + jl0] = acc3[mi][1] + db1;
            }
            int jl1 = jl0 + 8;
            if (jl1 < JC) {
                SD[cc0 * SD_STRF + jl1]       = acc3[mi][2] + db0;
                SD[(cc0 + 1) * SD_STRF + jl1] = acc3[mi][3] + db1;
            }
        }
    }
    __syncthreads();

    float* outb = out + (size_t)b * CCH * TOUT;
    #pragma unroll
    for (int cc = 0; cc < 4; cc++) {
        int c = 4 * w + cc;
        for (int jl = l; jl < JC; jl += 32) {
            int j = j0 + jl;
            if (j < TOUT) outb[c * TOUT + j] = SD[c * SD_STRF + jl];
        }
    }
}

extern "C" void kernel_launch(void* const* d_in, const int* in_sizes, int n_in,
                              void* d_out, int out_size)
{
    (void)in_sizes; (void)n_in; (void)out_size;
    const float* x      = (const float*)d_in[0];
    const float* sig_w  = (const float*)d_in[1];
    const float* sig_b  = (const float*)d_in[2];
    const float* gate_w = (const float*)d_in[3];
    const float* gate_b = (const float*)d_in[4];
    const float* out_w  = (const float*)d_in[5];
    const float* out_b  = (const float*)d_in[6];
    const float* skip_w = (const float*)d_in[7];
    const float* skip_b = (const float*)d_in[8];
    const float* dil_w  = (const float*)d_in[9];
    const float* dil_b  = (const float*)d_in[10];
    float* out = (float*)d_out;

    prep_weights<<<96, 256>>>(sig_w, gate_w, out_w, dil_w);

    cudaFuncSetAttribute(wavenet_h16_kernel,
                         cudaFuncAttributeMaxDynamicSharedMemorySize, SMEM_BYTES);
    dim3 grid(NCHUNK, BATCH, 1);
    wavenet_h16_kernel<<<grid, NTH, SMEM_BYTES>>>(
        x, sig_b, gate_b, out_b, skip_w, skip_b, dil_b, out);
}